// round 1
// baseline (speedup 1.0000x reference)
#include <cuda_runtime.h>
#include <math.h>

// ---------------- problem constants ----------------
#define BB      4
#define CIN     23
#define TT      8
#define HH      128
#define WW      128
#define PP      4
#define DM      256
#define DSTATE  16
#define DCONV   4
#define DINNER  512
#define HEADDIM 64
#define NHEADS  8
#define CONVDIM 544            // DINNER + 2*DSTATE
#define DPROJ   1064           // 2*DINNER + 2*DSTATE + NHEADS
#define HP      32
#define WP      32
#define LL      8192           // TT*HP*WP
#define MTOK    32768          // BB*LL
#define KPATCH  368            // CIN*PP*PP
#define QCHUNK  128
#define NCHUNK  64             // LL/QCHUNK
#define NOUT    (BB*CIN*TT*HH*WW)   // 12,058,624

// ---------------- scratch (static device memory; no allocation allowed) ----
__device__ __align__(128) float g_patchA [MTOK * KPATCH];     // im2col
__device__ __align__(128) float g_patchWT[KPATCH * DM];       // patch_w^T
__device__ __align__(128) float g_xs     [MTOK * DM];         // embedded tokens
__device__ __align__(128) float g_zx     [MTOK * DPROJ];      // zxbcdt
__device__ __align__(128) float g_xBCs   [MTOK * CONVDIM];    // silu(conv)
__device__ __align__(128) float g_dA     [MTOK * NHEADS];
__device__ __align__(128) float g_xdt    [MTOK * DINNER];
__device__ __align__(128) float g_Dt     [MTOK * NHEADS];     // in-chunk cum decay
__device__ __align__(128) float g_yloc   [MTOK * DINNER];
__device__ __align__(128) float g_S      [BB*NCHUNK*NHEADS*HEADDIM*DSTATE]; // chunk end states
__device__ __align__(128) float g_P      [BB*NCHUNK*NHEADS];  // chunk decay products
__device__ __align__(128) float g_hinit  [BB*NCHUNK*NHEADS*HEADDIM*DSTATE]; // chunk init states
__device__ __align__(128) float g_ynorm  [MTOK * DINNER];
__device__ __align__(128) float g_outseq [MTOK * DM];
__device__ __align__(128) float g_outpix [MTOK * KPATCH];

// ---------------- generic 128x128x8 SGEMM, 256 threads, 8x8 per thread ----
// C[M,N] = A[M,K] * B[K,N] (+ bias[N]).  M % 128 == 0, K % 8 == 0, N % 4 == 0.
__global__ __launch_bounds__(256) void sgemm128(
    const float* __restrict__ A, const float* __restrict__ B,
    float* __restrict__ C, int M, int N, int K, const float* __restrict__ bias)
{
    __shared__ __align__(16) float As[8][128];
    __shared__ __align__(16) float Bs[8][128];
    const int tid = threadIdx.x;
    const int bm  = blockIdx.y * 128;
    const int bn  = blockIdx.x * 128;
    const int tx  = tid & 15;         // col group
    const int ty  = tid >> 4;         // row group
    const int aRow = tid >> 1;        // 0..127
    const int aK   = (tid & 1) * 4;   // 0 or 4
    const int bRow = tid >> 5;        // 0..7
    const int bCol = (tid & 31) * 4;  // 0..124

    float acc[8][8];
#pragma unroll
    for (int i = 0; i < 8; i++)
#pragma unroll
        for (int j = 0; j < 8; j++) acc[i][j] = 0.f;

    for (int k0 = 0; k0 < K; k0 += 8) {
        float4 av = *(const float4*)&A[(size_t)(bm + aRow) * K + (k0 + aK)];
        As[aK + 0][aRow] = av.x;
        As[aK + 1][aRow] = av.y;
        As[aK + 2][aRow] = av.z;
        As[aK + 3][aRow] = av.w;

        float4 bv;
        if (bn + bCol < N)
            bv = *(const float4*)&B[(size_t)(k0 + bRow) * N + (bn + bCol)];
        else
            bv = make_float4(0.f, 0.f, 0.f, 0.f);
        *(float4*)&Bs[bRow][bCol] = bv;

        __syncthreads();
#pragma unroll
        for (int kk = 0; kk < 8; kk++) {
            float4 a0 = *(const float4*)&As[kk][ty * 8];
            float4 a1 = *(const float4*)&As[kk][ty * 8 + 4];
            float4 b0 = *(const float4*)&Bs[kk][tx * 8];
            float4 b1 = *(const float4*)&Bs[kk][tx * 8 + 4];
            float a[8] = {a0.x, a0.y, a0.z, a0.w, a1.x, a1.y, a1.z, a1.w};
            float b[8] = {b0.x, b0.y, b0.z, b0.w, b1.x, b1.y, b1.z, b1.w};
#pragma unroll
            for (int i = 0; i < 8; i++)
#pragma unroll
                for (int j = 0; j < 8; j++) acc[i][j] += a[i] * b[j];
        }
        __syncthreads();
    }

#pragma unroll
    for (int i = 0; i < 8; i++) {
        int row = bm + ty * 8 + i;
#pragma unroll
        for (int j = 0; j < 8; j++) {
            int col = bn + tx * 8 + j;
            if (col < N) {
                float v = acc[i][j];
                if (bias) v += bias[col];
                C[(size_t)row * N + col] = v;
            }
        }
    }
}

// ---------------- patch weight transpose: [256][368] -> [368][256] --------
__global__ void transpose_pw(const float* __restrict__ pw)
{
    int idx = blockIdx.x * blockDim.x + threadIdx.x;
    if (idx >= KPATCH * DM) return;
    int k = idx / DM, n = idx % DM;
    g_patchWT[idx] = pw[n * KPATCH + k];
}

// ---------------- im2col for patch embed ----------------------------------
__global__ void im2col_k(const float* __restrict__ x)
{
    int idx = blockIdx.x * blockDim.x + threadIdx.x;
    if (idx >= MTOK * KPATCH) return;
    int m = idx / KPATCH, k = idx % KPATCH;
    int c = k >> 4;
    int r = k & 15;
    int i = r >> 2, j = r & 3;
    int wp = m & 31, hp = (m >> 5) & 31, t = (m >> 10) & 7, b = m >> 13;
    g_patchA[idx] = x[(((size_t)(b * CIN + c) * TT + t) * HH + hp * 4 + i) * WW + wp * 4 + j];
}

// ---------------- conv1d(w=4) + silu + dt/dA/xdt prep ----------------------
__global__ __launch_bounds__(256) void conv_prep(
    const float* __restrict__ cw, const float* __restrict__ cb,
    const float* __restrict__ dtb, const float* __restrict__ alog)
{
    int m = blockIdx.x;
    int tid = threadIdx.x;
    int l = m & (LL - 1);
    __shared__ float sdt[NHEADS];
    if (tid < NHEADS) {
        float raw = g_zx[(size_t)m * DPROJ + DINNER + CONVDIM + tid] + dtb[tid];
        float dt = (raw > 20.f) ? raw : log1pf(expf(raw));
        sdt[tid] = dt;
        g_dA[m * NHEADS + tid] = expf(-expf(alog[tid]) * dt);
    }
    __syncthreads();
    for (int ch = tid; ch < CONVDIM; ch += 256) {
        float acc = cb[ch];
#pragma unroll
        for (int k = 0; k < DCONV; k++) {
            int ll = l - (DCONV - 1) + k;
            if (ll >= 0)
                acc += g_zx[(size_t)(m - (DCONV - 1) + k) * DPROJ + DINNER + ch] * cw[ch * DCONV + k];
        }
        float s = acc / (1.f + expf(-acc));
        g_xBCs[(size_t)m * CONVDIM + ch] = s;
        if (ch < DINNER) g_xdt[(size_t)m * DINNER + ch] = s * sdt[ch >> 6];
    }
}

// ---------------- scan phase 1: local chunk scans --------------------------
// grid = (NCHUNK, BB), block = 512 (thread = h*64 + p)
__global__ __launch_bounds__(512) void scan_phase1()
{
    int c = blockIdx.x, b = blockIdx.y;
    int tid = threadIdx.x;
    int h = tid >> 6, p = tid & 63;
    __shared__ float sBC[32];
    float hreg[DSTATE];
#pragma unroll
    for (int n = 0; n < DSTATE; n++) hreg[n] = 0.f;
    float runD = 1.f;
    int mbase = b * LL + c * QCHUNK;
    for (int i = 0; i < QCHUNK; i++) {
        int m = mbase + i;
        if (tid < 32) sBC[tid] = g_xBCs[(size_t)m * CONVDIM + DINNER + tid];
        __syncthreads();
        float dAv = g_dA[m * NHEADS + h];
        runD *= dAv;
        float xv = g_xdt[(size_t)m * DINNER + tid];
        float y = 0.f;
#pragma unroll
        for (int n = 0; n < DSTATE; n++) {
            hreg[n] = dAv * hreg[n] + xv * sBC[n];
            y += hreg[n] * sBC[16 + n];
        }
        g_yloc[(size_t)m * DINNER + tid] = y;
        if (p == 0) g_Dt[m * NHEADS + h] = runD;
        __syncthreads();
    }
    int sb = ((b * NCHUNK + c) * NHEADS + h) * HEADDIM + p;
#pragma unroll
    for (int n = 0; n < DSTATE; n++) g_S[(size_t)sb * DSTATE + n] = hreg[n];
    if (p == 0) g_P[(b * NCHUNK + c) * NHEADS + h] = runD;
}

// ---------------- scan phase 2: cross-chunk state recurrence ---------------
// grid = 32 (b*8+h), block = 1024 (p*16+n)
__global__ __launch_bounds__(1024) void scan_phase2()
{
    int b = blockIdx.x >> 3, h = blockIdx.x & 7;
    int tid = threadIdx.x;
    float val = 0.f;
    for (int c = 0; c < NCHUNK; c++) {
        size_t base = (size_t)((b * NCHUNK + c) * NHEADS + h) * (HEADDIM * DSTATE);
        g_hinit[base + tid] = val;
        val = g_P[(b * NCHUNK + c) * NHEADS + h] * val + g_S[base + tid];
    }
}

// ---------------- scan phase 3 + skip + gate + RMSnorm ---------------------
// grid = MTOK, block = 512 (d = h*64+p)
__global__ __launch_bounds__(512) void fuse_y_norm(
    const float* __restrict__ Dp, const float* __restrict__ nw)
{
    int m = blockIdx.x;
    int tid = threadIdx.x;
    int b = m >> 13;
    int l = m & (LL - 1);
    int c = l >> 7;
    int h = tid >> 6, p = tid & 63;
    __shared__ float sC[DSTATE];
    __shared__ float sred[17];
    if (tid < DSTATE) sC[tid] = g_xBCs[(size_t)m * CONVDIM + DINNER + DSTATE + tid];
    __syncthreads();

    const float* hi = &g_hinit[((size_t)((b * NCHUNK + c) * NHEADS + h) * HEADDIM + p) * DSTATE];
    float corr = 0.f;
#pragma unroll
    for (int n = 0; n < DSTATE; n++) corr += hi[n] * sC[n];

    float xh = g_xBCs[(size_t)m * CONVDIM + tid];
    float y = g_yloc[(size_t)m * DINNER + tid] + g_Dt[m * NHEADS + h] * corr + Dp[h] * xh;
    float z = g_zx[(size_t)m * DPROJ + tid];
    float yg = y * (z / (1.f + expf(-z)));

    float v = yg * yg;
#pragma unroll
    for (int o = 16; o; o >>= 1) v += __shfl_xor_sync(0xffffffffu, v, o);
    if ((tid & 31) == 0) sred[tid >> 5] = v;
    __syncthreads();
    if (tid < 32) {
        float tsum = (tid < 16) ? sred[tid] : 0.f;
#pragma unroll
        for (int o = 8; o; o >>= 1) tsum += __shfl_xor_sync(0xffffffffu, tsum, o);
        if (tid == 0) sred[16] = rsqrtf(tsum * (1.f / (float)DINNER) + 1e-5f);
    }
    __syncthreads();
    g_ynorm[(size_t)m * DINNER + tid] = yg * sred[16] * nw[tid];
}

// ---------------- scatter unembed patches + bias + residual ----------------
__global__ void scatter_out(const float* __restrict__ x, const float* __restrict__ ub,
                            float* __restrict__ out)
{
    int idx = blockIdx.x * blockDim.x + threadIdx.x;
    if (idx >= NOUT) return;
    int w = idx & 127;
    int hh = (idx >> 7) & 127;
    int t = (idx >> 14) & 7;
    int c = (idx / (HH * WW * TT)) % CIN;
    int b = idx / (CIN * TT * HH * WW);
    int wp = w >> 2, j = w & 3, hp = hh >> 2, i = hh & 3;
    int m = ((b * TT + t) * HP + hp) * WP + wp;
    int col = c * 16 + i * 4 + j;
    out[idx] = g_outpix[(size_t)m * KPATCH + col] + ub[c] + x[idx];
}

// ---------------- driver ---------------------------------------------------
extern "C" void kernel_launch(void* const* d_in, const int* in_sizes, int n_in,
                              void* d_out, int out_size)
{
    const float* x       = (const float*)d_in[0];
    const float* patch_w = (const float*)d_in[1];
    const float* patch_b = (const float*)d_in[2];
    const float* W_in    = (const float*)d_in[3];
    const float* conv_w  = (const float*)d_in[4];
    const float* conv_b  = (const float*)d_in[5];
    const float* dt_bias = (const float*)d_in[6];
    const float* A_log   = (const float*)d_in[7];
    const float* D_param = (const float*)d_in[8];
    const float* norm_w  = (const float*)d_in[9];
    const float* W_out   = (const float*)d_in[10];
    const float* unemb_w = (const float*)d_in[11];
    const float* unemb_b = (const float*)d_in[12];
    float* out = (float*)d_out;

    float *pA, *pWT, *pxs, *pzx, *pyn, *pos, *ppix;
    cudaGetSymbolAddress((void**)&pA,   g_patchA);
    cudaGetSymbolAddress((void**)&pWT,  g_patchWT);
    cudaGetSymbolAddress((void**)&pxs,  g_xs);
    cudaGetSymbolAddress((void**)&pzx,  g_zx);
    cudaGetSymbolAddress((void**)&pyn,  g_ynorm);
    cudaGetSymbolAddress((void**)&pos,  g_outseq);
    cudaGetSymbolAddress((void**)&ppix, g_outpix);

    // 1. prep patch weights + im2col
    transpose_pw<<<(KPATCH * DM + 255) / 256, 256>>>(patch_w);
    im2col_k<<<(MTOK * KPATCH + 255) / 256, 256>>>(x);

    // 2. patch embed: xs = A_patch @ patchW^T + patch_b
    sgemm128<<<dim3(2, MTOK / 128), 256>>>(pA, pWT, pxs, MTOK, DM, KPATCH, patch_b);

    // 3. in_proj: zxbcdt = xs @ W_in
    sgemm128<<<dim3((DPROJ + 127) / 128, MTOK / 128), 256>>>(pxs, W_in, pzx, MTOK, DPROJ, DM, nullptr);

    // 4. conv + silu + dt/dA/xdt
    conv_prep<<<MTOK, 256>>>(conv_w, conv_b, dt_bias, A_log);

    // 5. chunked SSM scan
    scan_phase1<<<dim3(NCHUNK, BB), 512>>>();
    scan_phase2<<<BB * NHEADS, 1024>>>();
    fuse_y_norm<<<MTOK, 512>>>(D_param, norm_w);

    // 6. out_proj: outseq = ynorm @ W_out
    sgemm128<<<dim3(2, MTOK / 128), 256>>>(pyn, W_out, pos, MTOK, DM, DINNER, nullptr);

    // 7. unembed: outpix = outseq @ unembed_w(flat [256,368])
    sgemm128<<<dim3(3, MTOK / 128), 256>>>(pos, unemb_w, ppix, MTOK, KPATCH, DM, nullptr);

    // 8. scatter + bias + residual
    scatter_out<<<(NOUT + 255) / 256, 256>>>(x, unemb_b, out);
}

// round 2
// speedup vs baseline: 1.7540x; 1.7540x over previous
#include <cuda_runtime.h>
#include <math.h>
#include <stdint.h>

// ---------------- problem constants ----------------
#define BB      4
#define CIN     23
#define TT      8
#define HH      128
#define WW      128
#define PP      4
#define DM      256
#define DSTATE  16
#define DCONV   4
#define DINNER  512
#define HEADDIM 64
#define NHEADS  8
#define CONVDIM 544            // DINNER + 2*DSTATE
#define DPROJ   1064           // 2*DINNER + 2*DSTATE + NHEADS
#define HP      32
#define WP      32
#define LL      8192           // TT*HP*WP
#define MTOK    32768          // BB*LL
#define KPATCH  368            // CIN*PP*PP
#define QCHUNK  128
#define NCHUNK  64             // LL/QCHUNK
#define NOUT    (BB*CIN*TT*HH*WW)   // 12,058,624

// ---------------- scratch (static device memory; no allocation allowed) ----
__device__ __align__(128) float g_patchA [MTOK * KPATCH];     // im2col
__device__ __align__(128) float g_patchWT[KPATCH * DM];       // patch_w^T
__device__ __align__(128) float g_xs     [MTOK * DM];         // embedded tokens
__device__ __align__(128) float g_zx     [MTOK * DPROJ];      // zxbcdt
__device__ __align__(128) float g_xBCs   [MTOK * CONVDIM];    // silu(conv)
__device__ __align__(128) float g_dA     [MTOK * NHEADS];
__device__ __align__(128) float g_xdt    [MTOK * DINNER];
__device__ __align__(128) float g_Dt     [MTOK * NHEADS];     // in-chunk cum decay
__device__ __align__(128) float g_yloc   [MTOK * DINNER];
__device__ __align__(128) float g_S      [BB*NCHUNK*NHEADS*HEADDIM*DSTATE]; // chunk end states
__device__ __align__(128) float g_P      [BB*NCHUNK*NHEADS];  // chunk decay products
__device__ __align__(128) float g_hinit  [BB*NCHUNK*NHEADS*HEADDIM*DSTATE]; // chunk init states
__device__ __align__(128) float g_ynorm  [MTOK * DINNER];
__device__ __align__(128) float g_outseq [MTOK * DM];
__device__ __align__(128) float g_outpix [MTOK * KPATCH];

// ---------------- tf32 helpers ---------------------------------------------
__device__ __forceinline__ uint32_t f2tf(float f) {
    uint32_t u;
    asm("cvt.rna.tf32.f32 %0, %1;" : "=r"(u) : "f"(f));
    return u;
}

__device__ __forceinline__ void mma8(float* c, const uint32_t* a, const uint32_t* b) {
    asm volatile(
        "mma.sync.aligned.m16n8k8.row.col.f32.tf32.tf32.f32 "
        "{%0,%1,%2,%3},{%4,%5,%6,%7},{%8,%9},{%0,%1,%2,%3};"
        : "+f"(c[0]), "+f"(c[1]), "+f"(c[2]), "+f"(c[3])
        : "r"(a[0]), "r"(a[1]), "r"(a[2]), "r"(a[3]), "r"(b[0]), "r"(b[1]));
}

// ---------------- TF32 tensor-core GEMM -------------------------------------
// C[M,N] = A[M,K] * B[K,N] (+ bias[N]).  M%128==0, K%16==0; N arbitrary (guarded).
// block = 256 thr (8 warps, 2x4), block tile 128x128, K-tile 16, warp tile 64x32.
#define AS_STRIDE 20
#define BS_STRIDE 136
__global__ __launch_bounds__(256) void tf32gemm(
    const float* __restrict__ A, const float* __restrict__ B,
    float* __restrict__ C, int M, int N, int K, const float* __restrict__ bias)
{
    __shared__ uint32_t As[128][AS_STRIDE];  // m-major, cols 0..15 used
    __shared__ uint32_t Bs[16][BS_STRIDE];   // k-major

    const int tid  = threadIdx.x;
    const int warp = tid >> 5, lane = tid & 31;
    const int warpM = warp >> 2, warpN = warp & 3;
    const int g  = lane >> 2;     // group id 0..7
    const int t4 = lane & 3;      // thread-in-group
    const int bm = blockIdx.y * 128;
    const int bn = blockIdx.x * 128;

    // global->shared indices
    const int aRow = tid >> 2;          // 0..63 (two batches of 64 rows)
    const int aK   = (tid & 3) * 4;     // 0,4,8,12
    const int bK   = tid >> 5;          // 0..7 (two batches of 8 k-rows)
    const int bCol = (tid & 31) * 4;    // 0..124

    float acc[4][4][4];
#pragma unroll
    for (int i = 0; i < 4; i++)
#pragma unroll
        for (int j = 0; j < 4; j++)
#pragma unroll
            for (int q = 0; q < 4; q++) acc[i][j][q] = 0.f;

    for (int k0 = 0; k0 < K; k0 += 16) {
        // load A tile 128x16 (tf32-converted), m-major
#pragma unroll
        for (int r = 0; r < 2; r++) {
            const int row = aRow + 64 * r;
            float4 v = *(const float4*)&A[(size_t)(bm + row) * K + (k0 + aK)];
            As[row][aK + 0] = f2tf(v.x);
            As[row][aK + 1] = f2tf(v.y);
            As[row][aK + 2] = f2tf(v.z);
            As[row][aK + 3] = f2tf(v.w);
        }
        // load B tile 16x128, k-major, guarded on N
#pragma unroll
        for (int r = 0; r < 2; r++) {
            const int kk = bK + 8 * r;
            float4 v = make_float4(0.f, 0.f, 0.f, 0.f);
            if (bn + bCol < N)
                v = *(const float4*)&B[(size_t)(k0 + kk) * N + (bn + bCol)];
            Bs[kk][bCol + 0] = f2tf(v.x);
            Bs[kk][bCol + 1] = f2tf(v.y);
            Bs[kk][bCol + 2] = f2tf(v.z);
            Bs[kk][bCol + 3] = f2tf(v.w);
        }
        __syncthreads();

#pragma unroll
        for (int kk = 0; kk < 16; kk += 8) {
            uint32_t af[4][4];
            uint32_t bf[4][2];
#pragma unroll
            for (int i = 0; i < 4; i++) {
                const int m0 = warpM * 64 + i * 16;
                af[i][0] = As[m0 + g    ][kk + t4];
                af[i][1] = As[m0 + g + 8][kk + t4];
                af[i][2] = As[m0 + g    ][kk + t4 + 4];
                af[i][3] = As[m0 + g + 8][kk + t4 + 4];
            }
#pragma unroll
            for (int j = 0; j < 4; j++) {
                const int n0 = warpN * 32 + j * 8;
                bf[j][0] = Bs[kk + t4    ][n0 + g];
                bf[j][1] = Bs[kk + t4 + 4][n0 + g];
            }
#pragma unroll
            for (int i = 0; i < 4; i++)
#pragma unroll
                for (int j = 0; j < 4; j++)
                    mma8(acc[i][j], af[i], bf[j]);
        }
        __syncthreads();
    }

    // epilogue
#pragma unroll
    for (int i = 0; i < 4; i++) {
        const int r0 = bm + warpM * 64 + i * 16 + g;
#pragma unroll
        for (int j = 0; j < 4; j++) {
            const int c0 = bn + warpN * 32 + j * 8 + t4 * 2;
            if (c0 < N) {
                float b0 = bias ? bias[c0] : 0.f;
                C[(size_t)r0 * N + c0]       = acc[i][j][0] + b0;
                C[(size_t)(r0 + 8) * N + c0] = acc[i][j][2] + b0;
                if (c0 + 1 < N) {
                    float b1 = bias ? bias[c0 + 1] : 0.f;
                    C[(size_t)r0 * N + c0 + 1]       = acc[i][j][1] + b1;
                    C[(size_t)(r0 + 8) * N + c0 + 1] = acc[i][j][3] + b1;
                }
            }
        }
    }
}

// ---------------- patch weight transpose: [256][368] -> [368][256] --------
__global__ void transpose_pw(const float* __restrict__ pw)
{
    int idx = blockIdx.x * blockDim.x + threadIdx.x;
    if (idx >= KPATCH * DM) return;
    int k = idx / DM, n = idx % DM;
    g_patchWT[idx] = pw[n * KPATCH + k];
}

// ---------------- im2col for patch embed ----------------------------------
__global__ void im2col_k(const float* __restrict__ x)
{
    int idx = blockIdx.x * blockDim.x + threadIdx.x;
    if (idx >= MTOK * KPATCH) return;
    int m = idx / KPATCH, k = idx % KPATCH;
    int c = k >> 4;
    int r = k & 15;
    int i = r >> 2, j = r & 3;
    int wp = m & 31, hp = (m >> 5) & 31, t = (m >> 10) & 7, b = m >> 13;
    g_patchA[idx] = x[(((size_t)(b * CIN + c) * TT + t) * HH + hp * 4 + i) * WW + wp * 4 + j];
}

// ---------------- conv1d(w=4) + silu + dt/dA/xdt prep ----------------------
__global__ __launch_bounds__(256) void conv_prep(
    const float* __restrict__ cw, const float* __restrict__ cb,
    const float* __restrict__ dtb, const float* __restrict__ alog)
{
    int m = blockIdx.x;
    int tid = threadIdx.x;
    int l = m & (LL - 1);
    __shared__ float sdt[NHEADS];
    if (tid < NHEADS) {
        float raw = g_zx[(size_t)m * DPROJ + DINNER + CONVDIM + tid] + dtb[tid];
        float dt = (raw > 20.f) ? raw : log1pf(expf(raw));
        sdt[tid] = dt;
        g_dA[m * NHEADS + tid] = expf(-expf(alog[tid]) * dt);
    }
    __syncthreads();
    for (int ch = tid; ch < CONVDIM; ch += 256) {
        float acc = cb[ch];
#pragma unroll
        for (int k = 0; k < DCONV; k++) {
            int ll = l - (DCONV - 1) + k;
            if (ll >= 0)
                acc += g_zx[(size_t)(m - (DCONV - 1) + k) * DPROJ + DINNER + ch] * cw[ch * DCONV + k];
        }
        float s = acc / (1.f + expf(-acc));
        g_xBCs[(size_t)m * CONVDIM + ch] = s;
        if (ch < DINNER) g_xdt[(size_t)m * DINNER + ch] = s * sdt[ch >> 6];
    }
}

// ---------------- scan phase 1: local chunk scans --------------------------
// grid = (NCHUNK, BB), block = 512 (thread = h*64 + p)
__global__ __launch_bounds__(512) void scan_phase1()
{
    int c = blockIdx.x, b = blockIdx.y;
    int tid = threadIdx.x;
    int h = tid >> 6, p = tid & 63;
    __shared__ float sBC[32];
    float hreg[DSTATE];
#pragma unroll
    for (int n = 0; n < DSTATE; n++) hreg[n] = 0.f;
    float runD = 1.f;
    int mbase = b * LL + c * QCHUNK;
    for (int i = 0; i < QCHUNK; i++) {
        int m = mbase + i;
        if (tid < 32) sBC[tid] = g_xBCs[(size_t)m * CONVDIM + DINNER + tid];
        __syncthreads();
        float dAv = g_dA[m * NHEADS + h];
        runD *= dAv;
        float xv = g_xdt[(size_t)m * DINNER + tid];
        float y = 0.f;
#pragma unroll
        for (int n = 0; n < DSTATE; n++) {
            hreg[n] = dAv * hreg[n] + xv * sBC[n];
            y += hreg[n] * sBC[16 + n];
        }
        g_yloc[(size_t)m * DINNER + tid] = y;
        if (p == 0) g_Dt[m * NHEADS + h] = runD;
        __syncthreads();
    }
    int sb = ((b * NCHUNK + c) * NHEADS + h) * HEADDIM + p;
#pragma unroll
    for (int n = 0; n < DSTATE; n++) g_S[(size_t)sb * DSTATE + n] = hreg[n];
    if (p == 0) g_P[(b * NCHUNK + c) * NHEADS + h] = runD;
}

// ---------------- scan phase 2: cross-chunk state recurrence ---------------
// grid = 32 (b*8+h), block = 1024 (p*16+n)
__global__ __launch_bounds__(1024) void scan_phase2()
{
    int b = blockIdx.x >> 3, h = blockIdx.x & 7;
    int tid = threadIdx.x;
    float val = 0.f;
    for (int c = 0; c < NCHUNK; c++) {
        size_t base = (size_t)((b * NCHUNK + c) * NHEADS + h) * (HEADDIM * DSTATE);
        g_hinit[base + tid] = val;
        val = g_P[(b * NCHUNK + c) * NHEADS + h] * val + g_S[base + tid];
    }
}

// ---------------- scan phase 3 + skip + gate + RMSnorm ---------------------
// grid = MTOK, block = 512 (d = h*64+p)
__global__ __launch_bounds__(512) void fuse_y_norm(
    const float* __restrict__ Dp, const float* __restrict__ nw)
{
    int m = blockIdx.x;
    int tid = threadIdx.x;
    int b = m >> 13;
    int l = m & (LL - 1);
    int c = l >> 7;
    int h = tid >> 6, p = tid & 63;
    __shared__ float sC[DSTATE];
    __shared__ float sred[17];
    if (tid < DSTATE) sC[tid] = g_xBCs[(size_t)m * CONVDIM + DINNER + DSTATE + tid];
    __syncthreads();

    const float* hi = &g_hinit[((size_t)((b * NCHUNK + c) * NHEADS + h) * HEADDIM + p) * DSTATE];
    float corr = 0.f;
#pragma unroll
    for (int n = 0; n < DSTATE; n++) corr += hi[n] * sC[n];

    float xh = g_xBCs[(size_t)m * CONVDIM + tid];
    float y = g_yloc[(size_t)m * DINNER + tid] + g_Dt[m * NHEADS + h] * corr + Dp[h] * xh;
    float z = g_zx[(size_t)m * DPROJ + tid];
    float yg = y * (z / (1.f + expf(-z)));

    float v = yg * yg;
#pragma unroll
    for (int o = 16; o; o >>= 1) v += __shfl_xor_sync(0xffffffffu, v, o);
    if ((tid & 31) == 0) sred[tid >> 5] = v;
    __syncthreads();
    if (tid < 32) {
        float tsum = (tid < 16) ? sred[tid] : 0.f;
#pragma unroll
        for (int o = 8; o; o >>= 1) tsum += __shfl_xor_sync(0xffffffffu, tsum, o);
        if (tid == 0) sred[16] = rsqrtf(tsum * (1.f / (float)DINNER) + 1e-5f);
    }
    __syncthreads();
    g_ynorm[(size_t)m * DINNER + tid] = yg * sred[16] * nw[tid];
}

// ---------------- scatter unembed patches + bias + residual ----------------
__global__ void scatter_out(const float* __restrict__ x, const float* __restrict__ ub,
                            float* __restrict__ out)
{
    int idx = blockIdx.x * blockDim.x + threadIdx.x;
    if (idx >= NOUT) return;
    int w = idx & 127;
    int hh = (idx >> 7) & 127;
    int t = (idx >> 14) & 7;
    int c = (idx / (HH * WW * TT)) % CIN;
    int b = idx / (CIN * TT * HH * WW);
    int wp = w >> 2, j = w & 3, hp = hh >> 2, i = hh & 3;
    int m = ((b * TT + t) * HP + hp) * WP + wp;
    int col = c * 16 + i * 4 + j;
    out[idx] = g_outpix[(size_t)m * KPATCH + col] + ub[c] + x[idx];
}

// ---------------- driver ---------------------------------------------------
extern "C" void kernel_launch(void* const* d_in, const int* in_sizes, int n_in,
                              void* d_out, int out_size)
{
    const float* x       = (const float*)d_in[0];
    const float* patch_w = (const float*)d_in[1];
    const float* patch_b = (const float*)d_in[2];
    const float* W_in    = (const float*)d_in[3];
    const float* conv_w  = (const float*)d_in[4];
    const float* conv_b  = (const float*)d_in[5];
    const float* dt_bias = (const float*)d_in[6];
    const float* A_log   = (const float*)d_in[7];
    const float* D_param = (const float*)d_in[8];
    const float* norm_w  = (const float*)d_in[9];
    const float* W_out   = (const float*)d_in[10];
    const float* unemb_w = (const float*)d_in[11];
    const float* unemb_b = (const float*)d_in[12];
    float* out = (float*)d_out;

    float *pA, *pWT, *pxs, *pzx, *pyn, *pos, *ppix;
    cudaGetSymbolAddress((void**)&pA,   g_patchA);
    cudaGetSymbolAddress((void**)&pWT,  g_patchWT);
    cudaGetSymbolAddress((void**)&pxs,  g_xs);
    cudaGetSymbolAddress((void**)&pzx,  g_zx);
    cudaGetSymbolAddress((void**)&pyn,  g_ynorm);
    cudaGetSymbolAddress((void**)&pos,  g_outseq);
    cudaGetSymbolAddress((void**)&ppix, g_outpix);

    // 1. prep patch weights + im2col
    transpose_pw<<<(KPATCH * DM + 255) / 256, 256>>>(patch_w);
    im2col_k<<<(MTOK * KPATCH + 255) / 256, 256>>>(x);

    // 2. patch embed: xs = A_patch @ patchW^T + patch_b
    tf32gemm<<<dim3(2, MTOK / 128), 256>>>(pA, pWT, pxs, MTOK, DM, KPATCH, patch_b);

    // 3. in_proj: zxbcdt = xs @ W_in
    tf32gemm<<<dim3((DPROJ + 127) / 128, MTOK / 128), 256>>>(pxs, W_in, pzx, MTOK, DPROJ, DM, nullptr);

    // 4. conv + silu + dt/dA/xdt
    conv_prep<<<MTOK, 256>>>(conv_w, conv_b, dt_bias, A_log);

    // 5. chunked SSM scan
    scan_phase1<<<dim3(NCHUNK, BB), 512>>>();
    scan_phase2<<<BB * NHEADS, 1024>>>();
    fuse_y_norm<<<MTOK, 512>>>(D_param, norm_w);

    // 6. out_proj: outseq = ynorm @ W_out
    tf32gemm<<<dim3(2, MTOK / 128), 256>>>(pyn, W_out, pos, MTOK, DM, DINNER, nullptr);

    // 7. unembed: outpix = outseq @ unembed_w(flat [256,368])
    tf32gemm<<<dim3(3, MTOK / 128), 256>>>(pos, unemb_w, ppix, MTOK, KPATCH, DM, nullptr);

    // 8. scatter + bias + residual
    scatter_out<<<(NOUT + 255) / 256, 256>>>(x, unemb_b, out);
}

// round 3
// speedup vs baseline: 1.9838x; 1.1311x over previous
#include <cuda_runtime.h>
#include <math.h>
#include <stdint.h>

// ---------------- problem constants ----------------
#define BB      4
#define CIN     23
#define TT      8
#define HH      128
#define WW      128
#define PP      4
#define DM      256
#define DSTATE  16
#define DCONV   4
#define DINNER  512
#define HEADDIM 64
#define NHEADS  8
#define CONVDIM 544            // DINNER + 2*DSTATE
#define DPROJ   1064           // 2*DINNER + 2*DSTATE + NHEADS
#define HP      32
#define WP      32
#define LL      8192           // TT*HP*WP
#define MTOK    32768          // BB*LL
#define KPATCH  368            // CIN*PP*PP
#define QCHUNK  64
#define NCHUNK  128            // LL/QCHUNK
#define NOUT    (BB*CIN*TT*HH*WW)   // 12,058,624

// ---------------- scratch (static device memory; no allocation allowed) ----
__device__ __align__(128) float g_patchA [MTOK * KPATCH];     // im2col
__device__ __align__(128) float g_patchWT[KPATCH * DM];       // patch_w^T
__device__ __align__(128) float g_xs     [MTOK * DM];         // embedded tokens
__device__ __align__(128) float g_zx     [MTOK * DPROJ];      // zxbcdt
__device__ __align__(128) float g_xBCs   [MTOK * CONVDIM];    // silu(conv)
__device__ __align__(128) float g_dA     [MTOK * NHEADS];
__device__ __align__(128) float g_xdt    [MTOK * DINNER];
__device__ __align__(128) float g_Dt     [MTOK * NHEADS];     // in-chunk cum decay
__device__ __align__(128) float g_yloc   [MTOK * DINNER];
__device__ __align__(128) float g_S      [BB*NCHUNK*NHEADS*HEADDIM*DSTATE]; // chunk end states
__device__ __align__(128) float g_P      [BB*NCHUNK*NHEADS];  // chunk decay products
__device__ __align__(128) float g_hinit  [BB*NCHUNK*NHEADS*HEADDIM*DSTATE]; // chunk init states
__device__ __align__(128) float g_ynorm  [MTOK * DINNER];
__device__ __align__(128) float g_outseq [MTOK * DM];
__device__ __align__(128) float g_outpix [MTOK * KPATCH];

// ---------------- tf32 helpers ---------------------------------------------
__device__ __forceinline__ uint32_t f2tf(float f) {
    uint32_t u;
    asm("cvt.rna.tf32.f32 %0, %1;" : "=r"(u) : "f"(f));
    return u;
}

__device__ __forceinline__ void mma8(float* c, const uint32_t* a, const uint32_t* b) {
    asm volatile(
        "mma.sync.aligned.m16n8k8.row.col.f32.tf32.tf32.f32 "
        "{%0,%1,%2,%3},{%4,%5,%6,%7},{%8,%9},{%0,%1,%2,%3};"
        : "+f"(c[0]), "+f"(c[1]), "+f"(c[2]), "+f"(c[3])
        : "r"(a[0]), "r"(a[1]), "r"(a[2]), "r"(a[3]), "r"(b[0]), "r"(b[1]));
}

// ---------------- TF32 tensor-core GEMM, double-buffered --------------------
// C[M,N] = A[M,K] * B[K,N] (+ bias[N]).  M%128==0, K%16==0; N arbitrary (guarded).
// block = 256 thr (8 warps, 2x4), block tile 128x128, K-tile 16, warp tile 64x32.
#define AS_STRIDE 20
#define BS_STRIDE 136
__global__ __launch_bounds__(256, 2) void tf32gemm(
    const float* __restrict__ A, const float* __restrict__ B,
    float* __restrict__ C, int M, int N, int K, const float* __restrict__ bias)
{
    __shared__ uint32_t As[2][128][AS_STRIDE];  // m-major, cols 0..15 used
    __shared__ uint32_t Bs[2][16][BS_STRIDE];   // k-major

    const int tid  = threadIdx.x;
    const int warp = tid >> 5, lane = tid & 31;
    const int warpM = warp >> 2, warpN = warp & 3;
    const int g  = lane >> 2;     // group id 0..7
    const int t4 = lane & 3;      // thread-in-group
    const int bm = blockIdx.y * 128;
    const int bn = blockIdx.x * 128;

    // global->shared indices
    const int aRow = tid >> 2;          // 0..63 (two batches of 64 rows)
    const int aK   = (tid & 3) * 4;     // 0,4,8,12
    const int bK   = tid >> 5;          // 0..7 (two batches of 8 k-rows)
    const int bCol = (tid & 31) * 4;    // 0..124
    const bool bOk = (bn + bCol) < N;

    float acc[4][4][4];
#pragma unroll
    for (int i = 0; i < 4; i++)
#pragma unroll
        for (int j = 0; j < 4; j++)
#pragma unroll
            for (int q = 0; q < 4; q++) acc[i][j][q] = 0.f;

    // ---- prologue: load k-tile 0 into buffer 0 ----
    {
        float4 av0 = *(const float4*)&A[(size_t)(bm + aRow) * K + aK];
        float4 av1 = *(const float4*)&A[(size_t)(bm + aRow + 64) * K + aK];
        float4 bv0 = make_float4(0.f,0.f,0.f,0.f), bv1 = bv0;
        if (bOk) {
            bv0 = *(const float4*)&B[(size_t)bK * N + (bn + bCol)];
            bv1 = *(const float4*)&B[(size_t)(bK + 8) * N + (bn + bCol)];
        }
        As[0][aRow   ][aK+0]=f2tf(av0.x); As[0][aRow   ][aK+1]=f2tf(av0.y);
        As[0][aRow   ][aK+2]=f2tf(av0.z); As[0][aRow   ][aK+3]=f2tf(av0.w);
        As[0][aRow+64][aK+0]=f2tf(av1.x); As[0][aRow+64][aK+1]=f2tf(av1.y);
        As[0][aRow+64][aK+2]=f2tf(av1.z); As[0][aRow+64][aK+3]=f2tf(av1.w);
        Bs[0][bK  ][bCol+0]=f2tf(bv0.x); Bs[0][bK  ][bCol+1]=f2tf(bv0.y);
        Bs[0][bK  ][bCol+2]=f2tf(bv0.z); Bs[0][bK  ][bCol+3]=f2tf(bv0.w);
        Bs[0][bK+8][bCol+0]=f2tf(bv1.x); Bs[0][bK+8][bCol+1]=f2tf(bv1.y);
        Bs[0][bK+8][bCol+2]=f2tf(bv1.z); Bs[0][bK+8][bCol+3]=f2tf(bv1.w);
    }
    __syncthreads();

    int p = 0;
    for (int k0 = 0; k0 < K; k0 += 16) {
        // prefetch next k-tile into registers (dummy re-load of tile 0 on last iter)
        const int kn = (k0 + 16 < K) ? (k0 + 16) : 0;
        float4 av0 = *(const float4*)&A[(size_t)(bm + aRow) * K + (kn + aK)];
        float4 av1 = *(const float4*)&A[(size_t)(bm + aRow + 64) * K + (kn + aK)];
        float4 bv0 = make_float4(0.f,0.f,0.f,0.f), bv1 = bv0;
        if (bOk) {
            bv0 = *(const float4*)&B[(size_t)(kn + bK) * N + (bn + bCol)];
            bv1 = *(const float4*)&B[(size_t)(kn + bK + 8) * N + (bn + bCol)];
        }

        // compute on buffer p
#pragma unroll
        for (int kk = 0; kk < 16; kk += 8) {
            uint32_t af[4][4];
            uint32_t bf[4][2];
#pragma unroll
            for (int i = 0; i < 4; i++) {
                const int m0 = warpM * 64 + i * 16;
                af[i][0] = As[p][m0 + g    ][kk + t4];
                af[i][1] = As[p][m0 + g + 8][kk + t4];
                af[i][2] = As[p][m0 + g    ][kk + t4 + 4];
                af[i][3] = As[p][m0 + g + 8][kk + t4 + 4];
            }
#pragma unroll
            for (int j = 0; j < 4; j++) {
                const int n0 = warpN * 32 + j * 8;
                bf[j][0] = Bs[p][kk + t4    ][n0 + g];
                bf[j][1] = Bs[p][kk + t4 + 4][n0 + g];
            }
#pragma unroll
            for (int i = 0; i < 4; i++)
#pragma unroll
                for (int j = 0; j < 4; j++)
                    mma8(acc[i][j], af[i], bf[j]);
        }

        // store prefetched tile into the other buffer
        const int q = p ^ 1;
        As[q][aRow   ][aK+0]=f2tf(av0.x); As[q][aRow   ][aK+1]=f2tf(av0.y);
        As[q][aRow   ][aK+2]=f2tf(av0.z); As[q][aRow   ][aK+3]=f2tf(av0.w);
        As[q][aRow+64][aK+0]=f2tf(av1.x); As[q][aRow+64][aK+1]=f2tf(av1.y);
        As[q][aRow+64][aK+2]=f2tf(av1.z); As[q][aRow+64][aK+3]=f2tf(av1.w);
        Bs[q][bK  ][bCol+0]=f2tf(bv0.x); Bs[q][bK  ][bCol+1]=f2tf(bv0.y);
        Bs[q][bK  ][bCol+2]=f2tf(bv0.z); Bs[q][bK  ][bCol+3]=f2tf(bv0.w);
        Bs[q][bK+8][bCol+0]=f2tf(bv1.x); Bs[q][bK+8][bCol+1]=f2tf(bv1.y);
        Bs[q][bK+8][bCol+2]=f2tf(bv1.z); Bs[q][bK+8][bCol+3]=f2tf(bv1.w);
        __syncthreads();
        p = q;
    }

    // epilogue (float2 stores; columns c0,c0+1 are adjacent & 8B-aligned)
#pragma unroll
    for (int i = 0; i < 4; i++) {
        const int r0 = bm + warpM * 64 + i * 16 + g;
#pragma unroll
        for (int j = 0; j < 4; j++) {
            const int c0 = bn + warpN * 32 + j * 8 + t4 * 2;
            if (c0 + 1 < N) {
                float2 bb = bias ? *(const float2*)&bias[c0] : make_float2(0.f, 0.f);
                *(float2*)&C[(size_t)r0 * N + c0] =
                    make_float2(acc[i][j][0] + bb.x, acc[i][j][1] + bb.y);
                *(float2*)&C[(size_t)(r0 + 8) * N + c0] =
                    make_float2(acc[i][j][2] + bb.x, acc[i][j][3] + bb.y);
            } else if (c0 < N) {
                float b0 = bias ? bias[c0] : 0.f;
                C[(size_t)r0 * N + c0]       = acc[i][j][0] + b0;
                C[(size_t)(r0 + 8) * N + c0] = acc[i][j][2] + b0;
            }
        }
    }
}

// ---------------- patch weight transpose: [256][368] -> [368][256] --------
__global__ void transpose_pw(const float* __restrict__ pw)
{
    int idx = blockIdx.x * blockDim.x + threadIdx.x;
    if (idx >= KPATCH * DM) return;
    int k = idx / DM, n = idx % DM;
    g_patchWT[idx] = pw[n * KPATCH + k];
}

// ---------------- im2col for patch embed ----------------------------------
__global__ void im2col_k(const float* __restrict__ x)
{
    int idx = blockIdx.x * blockDim.x + threadIdx.x;
    if (idx >= MTOK * KPATCH) return;
    int m = idx / KPATCH, k = idx % KPATCH;
    int c = k >> 4;
    int r = k & 15;
    int i = r >> 2, j = r & 3;
    int wp = m & 31, hp = (m >> 5) & 31, t = (m >> 10) & 7, b = m >> 13;
    g_patchA[idx] = x[(((size_t)(b * CIN + c) * TT + t) * HH + hp * 4 + i) * WW + wp * 4 + j];
}

// ---------------- conv1d(w=4) + silu + dt/dA/xdt prep ----------------------
__global__ __launch_bounds__(256) void conv_prep(
    const float* __restrict__ cw, const float* __restrict__ cb,
    const float* __restrict__ dtb, const float* __restrict__ alog)
{
    int m = blockIdx.x;
    int tid = threadIdx.x;
    int l = m & (LL - 1);
    __shared__ float sdt[NHEADS];
    if (tid < NHEADS) {
        float raw = g_zx[(size_t)m * DPROJ + DINNER + CONVDIM + tid] + dtb[tid];
        float dt = (raw > 20.f) ? raw : log1pf(expf(raw));
        sdt[tid] = dt;
        g_dA[m * NHEADS + tid] = expf(-expf(alog[tid]) * dt);
    }
    __syncthreads();
    for (int ch = tid; ch < CONVDIM; ch += 256) {
        float acc = cb[ch];
#pragma unroll
        for (int k = 0; k < DCONV; k++) {
            int ll = l - (DCONV - 1) + k;
            if (ll >= 0)
                acc += g_zx[(size_t)(m - (DCONV - 1) + k) * DPROJ + DINNER + ch] * cw[ch * DCONV + k];
        }
        float s = acc / (1.f + expf(-acc));
        g_xBCs[(size_t)m * CONVDIM + ch] = s;
        if (ch < DINNER) g_xdt[(size_t)m * DINNER + ch] = s * sdt[ch >> 6];
    }
}

// ---------------- scan phase 1: local chunk scans (warp-autonomous) --------
// grid = (NCHUNK, BB), block = 512. warp w: head h = w>>1, p-half = (w&1)*32.
__global__ __launch_bounds__(512) void scan_phase1()
{
    int c = blockIdx.x, b = blockIdx.y;
    int w = threadIdx.x >> 5, lane = threadIdx.x & 31;
    int h = w >> 1;
    int p = ((w & 1) << 5) + lane;
    int d = h * HEADDIM + p;
    __shared__ float sBC[16][32];
    float hreg[DSTATE];
#pragma unroll
    for (int n = 0; n < DSTATE; n++) hreg[n] = 0.f;
    float runD = 1.f;
    int mbase = b * LL + c * QCHUNK;
    for (int i = 0; i < QCHUNK; i++) {
        int m = mbase + i;
        sBC[w][lane] = g_xBCs[(size_t)m * CONVDIM + DINNER + lane];
        __syncwarp();
        float dAv = g_dA[m * NHEADS + h];
        runD *= dAv;
        float xv = g_xdt[(size_t)m * DINNER + d];
        float y0 = 0.f, y1 = 0.f;
#pragma unroll
        for (int n = 0; n < DSTATE; n += 2) {
            hreg[n]     = dAv * hreg[n]     + xv * sBC[w][n];
            hreg[n + 1] = dAv * hreg[n + 1] + xv * sBC[w][n + 1];
            y0 += hreg[n]     * sBC[w][16 + n];
            y1 += hreg[n + 1] * sBC[w][16 + n + 1];
        }
        g_yloc[(size_t)m * DINNER + d] = y0 + y1;
        if (p == 0) g_Dt[m * NHEADS + h] = runD;
        __syncwarp();
    }
    int sb = ((b * NCHUNK + c) * NHEADS + h) * HEADDIM + p;
#pragma unroll
    for (int n = 0; n < DSTATE; n++) g_S[(size_t)sb * DSTATE + n] = hreg[n];
    if (p == 0) g_P[(b * NCHUNK + c) * NHEADS + h] = runD;
}

// ---------------- scan phase 2: cross-chunk state recurrence ---------------
// grid = 32 (b*8+h), block = 1024 (p*16+n)
__global__ __launch_bounds__(1024) void scan_phase2()
{
    int b = blockIdx.x >> 3, h = blockIdx.x & 7;
    int tid = threadIdx.x;
    float val = 0.f;
    for (int c = 0; c < NCHUNK; c++) {
        size_t base = (size_t)((b * NCHUNK + c) * NHEADS + h) * (HEADDIM * DSTATE);
        g_hinit[base + tid] = val;
        val = g_P[(b * NCHUNK + c) * NHEADS + h] * val + g_S[base + tid];
    }
}

// ---------------- scan phase 3 + skip + gate + RMSnorm ---------------------
// grid = MTOK, block = 512 (d = h*64+p)
__global__ __launch_bounds__(512) void fuse_y_norm(
    const float* __restrict__ Dp, const float* __restrict__ nw)
{
    int m = blockIdx.x;
    int tid = threadIdx.x;
    int b = m >> 13;
    int l = m & (LL - 1);
    int c = l / QCHUNK;
    int h = tid >> 6, p = tid & 63;
    __shared__ float sC[DSTATE];
    __shared__ float sred[17];
    if (tid < DSTATE) sC[tid] = g_xBCs[(size_t)m * CONVDIM + DINNER + DSTATE + tid];
    __syncthreads();

    const float* hi = &g_hinit[((size_t)((b * NCHUNK + c) * NHEADS + h) * HEADDIM + p) * DSTATE];
    float corr = 0.f;
#pragma unroll
    for (int n = 0; n < DSTATE; n++) corr += hi[n] * sC[n];

    float xh = g_xBCs[(size_t)m * CONVDIM + tid];
    float y = g_yloc[(size_t)m * DINNER + tid] + g_Dt[m * NHEADS + h] * corr + Dp[h] * xh;
    float z = g_zx[(size_t)m * DPROJ + tid];
    float yg = y * (z / (1.f + expf(-z)));

    float v = yg * yg;
#pragma unroll
    for (int o = 16; o; o >>= 1) v += __shfl_xor_sync(0xffffffffu, v, o);
    if ((tid & 31) == 0) sred[tid >> 5] = v;
    __syncthreads();
    if (tid < 32) {
        float tsum = (tid < 16) ? sred[tid] : 0.f;
#pragma unroll
        for (int o = 8; o; o >>= 1) tsum += __shfl_xor_sync(0xffffffffu, tsum, o);
        if (tid == 0) sred[16] = rsqrtf(tsum * (1.f / (float)DINNER) + 1e-5f);
    }
    __syncthreads();
    g_ynorm[(size_t)m * DINNER + tid] = yg * sred[16] * nw[tid];
}

// ---------------- scatter unembed patches + bias + residual ----------------
__global__ void scatter_out(const float* __restrict__ x, const float* __restrict__ ub,
                            float* __restrict__ out)
{
    int idx = blockIdx.x * blockDim.x + threadIdx.x;
    if (idx >= NOUT) return;
    int w = idx & 127;
    int hh = (idx >> 7) & 127;
    int t = (idx >> 14) & 7;
    int c = (idx / (HH * WW * TT)) % CIN;
    int b = idx / (CIN * TT * HH * WW);
    int wp = w >> 2, j = w & 3, hp = hh >> 2, i = hh & 3;
    int m = ((b * TT + t) * HP + hp) * WP + wp;
    int col = c * 16 + i * 4 + j;
    out[idx] = g_outpix[(size_t)m * KPATCH + col] + ub[c] + x[idx];
}

// ---------------- driver ---------------------------------------------------
extern "C" void kernel_launch(void* const* d_in, const int* in_sizes, int n_in,
                              void* d_out, int out_size)
{
    const float* x       = (const float*)d_in[0];
    const float* patch_w = (const float*)d_in[1];
    const float* patch_b = (const float*)d_in[2];
    const float* W_in    = (const float*)d_in[3];
    const float* conv_w  = (const float*)d_in[4];
    const float* conv_b  = (const float*)d_in[5];
    const float* dt_bias = (const float*)d_in[6];
    const float* A_log   = (const float*)d_in[7];
    const float* D_param = (const float*)d_in[8];
    const float* norm_w  = (const float*)d_in[9];
    const float* W_out   = (const float*)d_in[10];
    const float* unemb_w = (const float*)d_in[11];
    const float* unemb_b = (const float*)d_in[12];
    float* out = (float*)d_out;

    float *pA, *pWT, *pxs, *pzx, *pyn, *pos, *ppix;
    cudaGetSymbolAddress((void**)&pA,   g_patchA);
    cudaGetSymbolAddress((void**)&pWT,  g_patchWT);
    cudaGetSymbolAddress((void**)&pxs,  g_xs);
    cudaGetSymbolAddress((void**)&pzx,  g_zx);
    cudaGetSymbolAddress((void**)&pyn,  g_ynorm);
    cudaGetSymbolAddress((void**)&pos,  g_outseq);
    cudaGetSymbolAddress((void**)&ppix, g_outpix);

    // 1. prep patch weights + im2col
    transpose_pw<<<(KPATCH * DM + 255) / 256, 256>>>(patch_w);
    im2col_k<<<(MTOK * KPATCH + 255) / 256, 256>>>(x);

    // 2. patch embed: xs = A_patch @ patchW^T + patch_b
    tf32gemm<<<dim3(2, MTOK / 128), 256>>>(pA, pWT, pxs, MTOK, DM, KPATCH, patch_b);

    // 3. in_proj: zxbcdt = xs @ W_in
    tf32gemm<<<dim3((DPROJ + 127) / 128, MTOK / 128), 256>>>(pxs, W_in, pzx, MTOK, DPROJ, DM, nullptr);

    // 4. conv + silu + dt/dA/xdt
    conv_prep<<<MTOK, 256>>>(conv_w, conv_b, dt_bias, A_log);

    // 5. chunked SSM scan
    scan_phase1<<<dim3(NCHUNK, BB), 512>>>();
    scan_phase2<<<BB * NHEADS, 1024>>>();
    fuse_y_norm<<<MTOK, 512>>>(D_param, norm_w);

    // 6. out_proj: outseq = ynorm @ W_out
    tf32gemm<<<dim3(2, MTOK / 128), 256>>>(pyn, W_out, pos, MTOK, DM, DINNER, nullptr);

    // 7. unembed: outpix = outseq @ unembed_w(flat [256,368])
    tf32gemm<<<dim3(3, MTOK / 128), 256>>>(pos, unemb_w, ppix, MTOK, KPATCH, DM, nullptr);

    // 8. scatter + bias + residual
    scatter_out<<<(NOUT + 255) / 256, 256>>>(x, unemb_b, out);
}

// round 4
// speedup vs baseline: 2.4728x; 1.2465x over previous
#include <cuda_runtime.h>
#include <math.h>
#include <stdint.h>

// ---------------- problem constants ----------------
#define BB      4
#define CIN     23
#define TT      8
#define HH      128
#define WW      128
#define DM      256
#define DSTATE  16
#define DCONV   4
#define DINNER  512
#define HEADDIM 64
#define NHEADS  8
#define CONVDIM 544
#define DPROJ   1064
#define HP      32
#define WP      32
#define LL      8192
#define MTOK    32768
#define KPATCH  368
#define QCHUNK  64
#define NCHUNK  128
#define NOUT    (BB*CIN*TT*HH*WW)

// ---------------- scratch ----------------
__device__ __align__(128) float g_patchWT[KPATCH * DM];       // patch_w^T (tf32-rounded)
__device__ __align__(128) float g_Win_r [DM * DPROJ];         // tf32-rounded W_in
__device__ __align__(128) float g_Wout_r[DINNER * DM];        // tf32-rounded W_out
__device__ __align__(128) float g_Wun_r [DM * KPATCH];        // tf32-rounded unembed_w
__device__ __align__(128) float g_xs    [MTOK * DM];          // tokens (tf32-rounded)
__device__ __align__(128) float g_zx    [MTOK * DPROJ];
__device__ __align__(128) float g_xBCs  [MTOK * CONVDIM];
__device__ __align__(128) float g_dA    [MTOK * NHEADS];
__device__ __align__(128) float g_dts   [MTOK * NHEADS];
__device__ __align__(128) float g_xdt   [MTOK * DINNER];
__device__ __align__(128) float g_Dt    [MTOK * NHEADS];
__device__ __align__(128) float g_yloc  [MTOK * DINNER];
__device__ __align__(128) float g_S     [BB*NCHUNK*NHEADS*HEADDIM*DSTATE];
__device__ __align__(128) float g_P     [BB*NCHUNK*NHEADS];
__device__ __align__(128) float g_hinit [BB*NCHUNK*NHEADS*HEADDIM*DSTATE];
__device__ __align__(128) float g_ynorm [MTOK * DINNER];      // tf32-rounded
__device__ __align__(128) float g_outseq[MTOK * DM];          // tf32-rounded

// ---------------- helpers ---------------------------------------------------
__device__ __forceinline__ uint32_t f2tf(float f) {
    uint32_t u;
    asm("cvt.rna.tf32.f32 %0, %1;" : "=r"(u) : "f"(f));
    return u;
}
__device__ __forceinline__ float f2tf_f(float f) { return __uint_as_float(f2tf(f)); }

__device__ __forceinline__ void mma8(float* c, const uint32_t* a, const uint32_t* b) {
    asm volatile(
        "mma.sync.aligned.m16n8k8.row.col.f32.tf32.tf32.f32 "
        "{%0,%1,%2,%3},{%4,%5,%6,%7},{%8,%9},{%0,%1,%2,%3};"
        : "+f"(c[0]), "+f"(c[1]), "+f"(c[2]), "+f"(c[3])
        : "r"(a[0]), "r"(a[1]), "r"(a[2]), "r"(a[3]), "r"(b[0]), "r"(b[1]));
}
__device__ __forceinline__ void ldsm4(uint32_t* r, uint32_t addr) {
    asm volatile("ldmatrix.sync.aligned.m8n8.x4.shared.b16 {%0,%1,%2,%3},[%4];"
                 : "=r"(r[0]), "=r"(r[1]), "=r"(r[2]), "=r"(r[3]) : "r"(addr));
}
__device__ __forceinline__ void cpasync16(uint32_t saddr, const void* gaddr) {
    asm volatile("cp.async.cg.shared.global [%0], [%1], 16;\n" :: "r"(saddr), "l"(gaddr));
}
__device__ __forceinline__ void cpasync16z(uint32_t saddr, const void* gaddr, int sz) {
    asm volatile("cp.async.cg.shared.global [%0], [%1], 16, %2;\n"
                 :: "r"(saddr), "l"(gaddr), "r"(sz));
}
#define CP_COMMIT() asm volatile("cp.async.commit_group;\n" ::: "memory")
#define CP_WAIT2()  asm volatile("cp.async.wait_group 2;\n" ::: "memory")

// stage sizes in floats
#define ASTG 2560   // 128*20
#define BSTG 2176   // 16*136
#define GEMM_SMEM ((4*ASTG + 4*BSTG) * 4)   // 75776 bytes

// ---------------- generic cp.async TF32 GEMM (inputs pre-rounded) ----------
// C[M,N] = A[M,K]*B[K,N]; M%128==0, K%16==0 (K/16 >= 3); N guarded.
__global__ __launch_bounds__(256, 2) void gemm_cp(
    const float* __restrict__ A, const float* __restrict__ B,
    float* __restrict__ C, int M, int N, int K, int roundOut)
{
    extern __shared__ uint32_t sm[];
    const uint32_t smb = (uint32_t)__cvta_generic_to_shared(sm);
    const int tid = threadIdx.x, warp = tid >> 5, lane = tid & 31;
    const int warpM = warp >> 2, warpN = warp & 3;
    const int g = lane >> 2, t4 = lane & 3;
    const int bm = blockIdx.y * 128, bn = blockIdx.x * 128;
    const int aRow = tid >> 2, aK = (tid & 3) * 4;
    const int bK = tid >> 5, bCol = (tid & 31) * 4;
    const int bsz = (bn + bCol) < N ? 16 : 0;
    const int T = K >> 4;

    float acc[4][4][4];
#pragma unroll
    for (int i = 0; i < 4; i++)
#pragma unroll
        for (int j = 0; j < 4; j++)
#pragma unroll
            for (int q = 0; q < 4; q++) acc[i][j][q] = 0.f;

#define ISSUE(t) { \
    int s_ = (t) & 3; int k0_ = (t) << 4; \
    uint32_t sa_ = smb + s_ * (ASTG * 4); \
    uint32_t sb_ = smb + (4 * ASTG * 4) + s_ * (BSTG * 4); \
    cpasync16(sa_ + (aRow * 20 + aK) * 4, &A[(size_t)(bm + aRow) * K + k0_ + aK]); \
    cpasync16(sa_ + ((aRow + 64) * 20 + aK) * 4, &A[(size_t)(bm + aRow + 64) * K + k0_ + aK]); \
    cpasync16z(sb_ + (bK * 136 + bCol) * 4, &B[(size_t)(k0_ + bK) * N + bn + bCol], bsz); \
    cpasync16z(sb_ + ((bK + 8) * 136 + bCol) * 4, &B[(size_t)(k0_ + bK + 8) * N + bn + bCol], bsz); }

    ISSUE(0); CP_COMMIT();
    ISSUE(1); CP_COMMIT();
    ISSUE(2); CP_COMMIT();
    CP_WAIT2();
    __syncthreads();

    for (int t = 0; t < T; t++) {
        const int s = t & 3;
        const uint32_t sa = smb + s * (ASTG * 4);
        const uint32_t* Bs = sm + 4 * ASTG + s * BSTG;
#pragma unroll
        for (int kk = 0; kk < 16; kk += 8) {
            uint32_t af[4][4], bf[4][2];
#pragma unroll
            for (int i = 0; i < 4; i++) {
                const int m0 = warpM * 64 + i * 16;
                ldsm4(af[i], sa + ((m0 + (lane & 15)) * 20 + kk + ((lane & 16) >> 2)) * 4);
            }
#pragma unroll
            for (int j = 0; j < 4; j++) {
                const int n0 = warpN * 32 + j * 8;
                bf[j][0] = Bs[(kk + t4) * 136 + n0 + g];
                bf[j][1] = Bs[(kk + t4 + 4) * 136 + n0 + g];
            }
#pragma unroll
            for (int i = 0; i < 4; i++)
#pragma unroll
                for (int j = 0; j < 4; j++)
                    mma8(acc[i][j], af[i], bf[j]);
        }
        if (t + 3 < T) ISSUE(t + 3);
        CP_COMMIT();
        CP_WAIT2();
        __syncthreads();
    }
#undef ISSUE

#pragma unroll
    for (int i = 0; i < 4; i++) {
        const int r0 = bm + warpM * 64 + i * 16 + g;
#pragma unroll
        for (int j = 0; j < 4; j++) {
            const int c0 = bn + warpN * 32 + j * 8 + t4 * 2;
            if (c0 + 1 < N) {
                float v0 = acc[i][j][0], v1 = acc[i][j][1];
                float v2 = acc[i][j][2], v3 = acc[i][j][3];
                if (roundOut) { v0 = f2tf_f(v0); v1 = f2tf_f(v1); v2 = f2tf_f(v2); v3 = f2tf_f(v3); }
                *(float2*)&C[(size_t)r0 * N + c0] = make_float2(v0, v1);
                *(float2*)&C[(size_t)(r0 + 8) * N + c0] = make_float2(v2, v3);
            } else if (c0 < N) {
                float v0 = acc[i][j][0], v2 = acc[i][j][2];
                if (roundOut) { v0 = f2tf_f(v0); v2 = f2tf_f(v2); }
                C[(size_t)r0 * N + c0] = v0;
                C[(size_t)(r0 + 8) * N + c0] = v2;
            }
        }
    }
}

// ---------------- unembed GEMM with fused scatter + residual epilogue ------
__global__ __launch_bounds__(256, 2) void gemm_unembed(
    const float* __restrict__ A, const float* __restrict__ B,
    const float* __restrict__ x, const float* __restrict__ ub,
    float* __restrict__ out)
{
    const int M = MTOK, N = KPATCH, K = DM;
    extern __shared__ uint32_t sm[];
    const uint32_t smb = (uint32_t)__cvta_generic_to_shared(sm);
    const int tid = threadIdx.x, warp = tid >> 5, lane = tid & 31;
    const int warpM = warp >> 2, warpN = warp & 3;
    const int g = lane >> 2, t4 = lane & 3;
    const int bm = blockIdx.y * 128, bn = blockIdx.x * 128;
    const int aRow = tid >> 2, aK = (tid & 3) * 4;
    const int bK = tid >> 5, bCol = (tid & 31) * 4;
    const int bsz = (bn + bCol) < N ? 16 : 0;
    const int T = K >> 4;

    float acc[4][4][4];
#pragma unroll
    for (int i = 0; i < 4; i++)
#pragma unroll
        for (int j = 0; j < 4; j++)
#pragma unroll
            for (int q = 0; q < 4; q++) acc[i][j][q] = 0.f;

#define ISSUE(t) { \
    int s_ = (t) & 3; int k0_ = (t) << 4; \
    uint32_t sa_ = smb + s_ * (ASTG * 4); \
    uint32_t sb_ = smb + (4 * ASTG * 4) + s_ * (BSTG * 4); \
    cpasync16(sa_ + (aRow * 20 + aK) * 4, &A[(size_t)(bm + aRow) * K + k0_ + aK]); \
    cpasync16(sa_ + ((aRow + 64) * 20 + aK) * 4, &A[(size_t)(bm + aRow + 64) * K + k0_ + aK]); \
    cpasync16z(sb_ + (bK * 136 + bCol) * 4, &B[(size_t)(k0_ + bK) * N + bn + bCol], bsz); \
    cpasync16z(sb_ + ((bK + 8) * 136 + bCol) * 4, &B[(size_t)(k0_ + bK + 8) * N + bn + bCol], bsz); }

    ISSUE(0); CP_COMMIT();
    ISSUE(1); CP_COMMIT();
    ISSUE(2); CP_COMMIT();
    CP_WAIT2();
    __syncthreads();

    for (int t = 0; t < T; t++) {
        const int s = t & 3;
        const uint32_t sa = smb + s * (ASTG * 4);
        const uint32_t* Bs = sm + 4 * ASTG + s * BSTG;
#pragma unroll
        for (int kk = 0; kk < 16; kk += 8) {
            uint32_t af[4][4], bf[4][2];
#pragma unroll
            for (int i = 0; i < 4; i++) {
                const int m0 = warpM * 64 + i * 16;
                ldsm4(af[i], sa + ((m0 + (lane & 15)) * 20 + kk + ((lane & 16) >> 2)) * 4);
            }
#pragma unroll
            for (int j = 0; j < 4; j++) {
                const int n0 = warpN * 32 + j * 8;
                bf[j][0] = Bs[(kk + t4) * 136 + n0 + g];
                bf[j][1] = Bs[(kk + t4 + 4) * 136 + n0 + g];
            }
#pragma unroll
            for (int i = 0; i < 4; i++)
#pragma unroll
                for (int j = 0; j < 4; j++)
                    mma8(acc[i][j], af[i], bf[j]);
        }
        if (t + 3 < T) ISSUE(t + 3);
        CP_COMMIT();
        CP_WAIT2();
        __syncthreads();
    }
#undef ISSUE

    // scatter epilogue: row -> (b,t,hp,wp), col -> (c,i,j); out += ub + x
#pragma unroll
    for (int i = 0; i < 4; i++) {
        const int r0 = bm + warpM * 64 + i * 16 + g;
        const int wp = r0 & 31, hp = (r0 >> 5) & 31, tt = (r0 >> 10) & 7, b = r0 >> 13;
#pragma unroll
        for (int j = 0; j < 4; j++) {
            const int c0 = bn + warpN * 32 + j * 8 + t4 * 2;
            if (c0 < N) {
                const int c = c0 >> 4, i4 = (c0 >> 2) & 3, j0 = c0 & 3;
                const size_t o = ((((size_t)(b * CIN + c) * TT + tt) * HH) + hp * 4 + i4) * WW
                               + (size_t)wp * 4 + j0;
                const float ubv = ub[c];
                float2 xv0 = *(const float2*)&x[o];
                float2 xv1 = *(const float2*)&x[o + 32];
                *(float2*)&out[o]      = make_float2(acc[i][j][0] + ubv + xv0.x,
                                                     acc[i][j][1] + ubv + xv0.y);
                *(float2*)&out[o + 32] = make_float2(acc[i][j][2] + ubv + xv1.x,
                                                     acc[i][j][3] + ubv + xv1.y);
            }
        }
    }
}

// ---------------- patch-embed GEMM with fused im2col A-gather --------------
// C = im2col(x)[MTOK,368] @ patchWT[368,256] + bias, output tf32-rounded.
__global__ __launch_bounds__(256, 2) void patch_gemm(
    const float* __restrict__ x, const float* __restrict__ B,
    float* __restrict__ C, const float* __restrict__ bias)
{
    const int K = KPATCH, N = DM;
    __shared__ uint32_t As[2][128][20];
    __shared__ uint32_t Bs[2][16][136];
    const int tid = threadIdx.x, warp = tid >> 5, lane = tid & 31;
    const int warpM = warp >> 2, warpN = warp & 3;
    const int g = lane >> 2, t4 = lane & 3;
    const int bm = blockIdx.y * 128, bn = blockIdx.x * 128;
    const int aRow = tid >> 2, aK = (tid & 3) * 4;
    const int bK = tid >> 5, bCol = (tid & 31) * 4;

    const uint32_t asb = (uint32_t)__cvta_generic_to_shared(&As[0][0][0]);

    // gather offset for (row, k): j in [0,4) contiguous in x
    auto xoff = [&](int row, int k) -> size_t {
        const int c = k >> 4, i = (k >> 2) & 3;
        const int wp = row & 31, hp = (row >> 5) & 31, tt = (row >> 10) & 7, b = row >> 13;
        return ((((size_t)(b * CIN + c) * TT + tt) * HH) + hp * 4 + i) * WW + (size_t)wp * 4;
    };

    float acc[4][4][4];
#pragma unroll
    for (int i = 0; i < 4; i++)
#pragma unroll
        for (int j = 0; j < 4; j++)
#pragma unroll
            for (int q = 0; q < 4; q++) acc[i][j][q] = 0.f;

    {
        float4 av0 = *(const float4*)&x[xoff(bm + aRow, aK)];
        float4 av1 = *(const float4*)&x[xoff(bm + aRow + 64, aK)];
        float4 bv0 = *(const float4*)&B[(size_t)bK * N + bn + bCol];
        float4 bv1 = *(const float4*)&B[(size_t)(bK + 8) * N + bn + bCol];
        As[0][aRow][aK+0]=f2tf(av0.x); As[0][aRow][aK+1]=f2tf(av0.y);
        As[0][aRow][aK+2]=f2tf(av0.z); As[0][aRow][aK+3]=f2tf(av0.w);
        As[0][aRow+64][aK+0]=f2tf(av1.x); As[0][aRow+64][aK+1]=f2tf(av1.y);
        As[0][aRow+64][aK+2]=f2tf(av1.z); As[0][aRow+64][aK+3]=f2tf(av1.w);
        *(float4*)&Bs[0][bK][bCol]   = bv0;
        *(float4*)&Bs[0][bK+8][bCol] = bv1;
    }
    __syncthreads();

    int p = 0;
    for (int k0 = 0; k0 < K; k0 += 16) {
        const int kn = (k0 + 16 < K) ? (k0 + 16) : 0;
        float4 av0 = *(const float4*)&x[xoff(bm + aRow, kn + aK)];
        float4 av1 = *(const float4*)&x[xoff(bm + aRow + 64, kn + aK)];
        float4 bv0 = *(const float4*)&B[(size_t)(kn + bK) * N + bn + bCol];
        float4 bv1 = *(const float4*)&B[(size_t)(kn + bK + 8) * N + bn + bCol];

        const uint32_t sa = asb + (uint32_t)p * (128 * 20 * 4);
#pragma unroll
        for (int kk = 0; kk < 16; kk += 8) {
            uint32_t af[4][4], bf[4][2];
#pragma unroll
            for (int i = 0; i < 4; i++) {
                const int m0 = warpM * 64 + i * 16;
                ldsm4(af[i], sa + ((m0 + (lane & 15)) * 20 + kk + ((lane & 16) >> 2)) * 4);
            }
#pragma unroll
            for (int j = 0; j < 4; j++) {
                const int n0 = warpN * 32 + j * 8;
                bf[j][0] = Bs[p][kk + t4][n0 + g];
                bf[j][1] = Bs[p][kk + t4 + 4][n0 + g];
            }
#pragma unroll
            for (int i = 0; i < 4; i++)
#pragma unroll
                for (int j = 0; j < 4; j++)
                    mma8(acc[i][j], af[i], bf[j]);
        }

        const int q = p ^ 1;
        As[q][aRow][aK+0]=f2tf(av0.x); As[q][aRow][aK+1]=f2tf(av0.y);
        As[q][aRow][aK+2]=f2tf(av0.z); As[q][aRow][aK+3]=f2tf(av0.w);
        As[q][aRow+64][aK+0]=f2tf(av1.x); As[q][aRow+64][aK+1]=f2tf(av1.y);
        As[q][aRow+64][aK+2]=f2tf(av1.z); As[q][aRow+64][aK+3]=f2tf(av1.w);
        *(float4*)&Bs[q][bK][bCol]   = bv0;
        *(float4*)&Bs[q][bK+8][bCol] = bv1;
        __syncthreads();
        p = q;
    }

#pragma unroll
    for (int i = 0; i < 4; i++) {
        const int r0 = bm + warpM * 64 + i * 16 + g;
#pragma unroll
        for (int j = 0; j < 4; j++) {
            const int c0 = bn + warpN * 32 + j * 8 + t4 * 2;
            float2 bb = *(const float2*)&bias[c0];
            *(float2*)&C[(size_t)r0 * N + c0] =
                make_float2(f2tf_f(acc[i][j][0] + bb.x), f2tf_f(acc[i][j][1] + bb.y));
            *(float2*)&C[(size_t)(r0 + 8) * N + c0] =
                make_float2(f2tf_f(acc[i][j][2] + bb.x), f2tf_f(acc[i][j][3] + bb.y));
        }
    }
}

// ---------------- weight prep ----------------------------------------------
__global__ void transpose_pw(const float* __restrict__ pw)
{
    int idx = blockIdx.x * blockDim.x + threadIdx.x;
    if (idx >= KPATCH * DM) return;
    int k = idx / DM, n = idx % DM;
    g_patchWT[idx] = f2tf_f(pw[n * KPATCH + k]);
}
__global__ void round_copy(const float* __restrict__ src, float* __restrict__ dst, int n)
{
    int i = blockIdx.x * blockDim.x + threadIdx.x;
    if (i < n) dst[i] = f2tf_f(src[i]);
}

// ---------------- dt / dA prep ----------------------------------------------
__global__ void dt_prep(const float* __restrict__ dtb, const float* __restrict__ alog)
{
    int idx = blockIdx.x * blockDim.x + threadIdx.x;
    if (idx >= MTOK * NHEADS) return;
    int m = idx >> 3, hh = idx & 7;
    float raw = g_zx[(size_t)m * DPROJ + DINNER + CONVDIM + hh] + dtb[hh];
    float dt = (raw > 20.f) ? raw : log1pf(expf(raw));
    g_dts[idx] = dt;
    g_dA[idx] = expf(-expf(alog[hh]) * dt);
}

// ---------------- conv1d(w=4) + silu + xdt, float4 ---------------------------
__global__ __launch_bounds__(256) void conv_v4(
    const float* __restrict__ cw, const float* __restrict__ cb)
{
    int t = blockIdx.x * 256 + threadIdx.x;
    if (t >= MTOK * 136) return;
    int m = t / 136, c4 = (t % 136) * 4;
    int l = m & (LL - 1);

    float4 w0 = *(const float4*)&cw[(c4 + 0) * 4];
    float4 w1 = *(const float4*)&cw[(c4 + 1) * 4];
    float4 w2 = *(const float4*)&cw[(c4 + 2) * 4];
    float4 w3 = *(const float4*)&cw[(c4 + 3) * 4];
    float4 acc = *(const float4*)&cb[c4];

#pragma unroll
    for (int kk = 0; kk < DCONV; kk++) {
        if (l - 3 + kk >= 0) {
            float4 v = *(const float4*)&g_zx[(size_t)(m - 3 + kk) * DPROJ + DINNER + c4];
            float wk0 = ((const float*)&w0)[kk];
            float wk1 = ((const float*)&w1)[kk];
            float wk2 = ((const float*)&w2)[kk];
            float wk3 = ((const float*)&w3)[kk];
            acc.x += v.x * wk0; acc.y += v.y * wk1;
            acc.z += v.z * wk2; acc.w += v.w * wk3;
        }
    }
    float4 s;
    s.x = acc.x / (1.f + expf(-acc.x));
    s.y = acc.y / (1.f + expf(-acc.y));
    s.z = acc.z / (1.f + expf(-acc.z));
    s.w = acc.w / (1.f + expf(-acc.w));
    *(float4*)&g_xBCs[(size_t)m * CONVDIM + c4] = s;
    if (c4 < DINNER) {
        float dtv = g_dts[m * NHEADS + (c4 >> 6)];
        float4 o = make_float4(s.x * dtv, s.y * dtv, s.z * dtv, s.w * dtv);
        *(float4*)&g_xdt[(size_t)m * DINNER + c4] = o;
    }
}

// ---------------- scan phase 1 (warp-autonomous, prefetched) ----------------
__global__ __launch_bounds__(512) void scan_phase1()
{
    const int c = blockIdx.x, b = blockIdx.y;
    const int w = threadIdx.x >> 5, lane = threadIdx.x & 31;
    const int h = w >> 1;
    const int p = ((w & 1) << 5) + lane;
    const int d = h * HEADDIM + p;
    __shared__ float sBC[16][2][32];
    float hreg[DSTATE];
#pragma unroll
    for (int n = 0; n < DSTATE; n++) hreg[n] = 0.f;
    float runD = 1.f;
    const int m0 = b * LL + c * QCHUNK;

    float xv = g_xdt[(size_t)m0 * DINNER + d];
    float bc = g_xBCs[(size_t)m0 * CONVDIM + DINNER + lane];
    float da = g_dA[m0 * NHEADS + h];
    sBC[w][0][lane] = bc;
    __syncwarp();

    int buf = 0;
    for (int i = 0; i < QCHUNK; i++) {
        const int m = m0 + i;
        float xv1 = 0.f, bc1 = 0.f, da1 = 0.f;
        if (i + 1 < QCHUNK) {
            xv1 = g_xdt[(size_t)(m + 1) * DINNER + d];
            bc1 = g_xBCs[(size_t)(m + 1) * CONVDIM + DINNER + lane];
            da1 = g_dA[(m + 1) * NHEADS + h];
        }
        runD *= da;
        float y0 = 0.f, y1 = 0.f;
#pragma unroll
        for (int n = 0; n < DSTATE; n += 2) {
            hreg[n]     = da * hreg[n]     + xv * sBC[w][buf][n];
            hreg[n + 1] = da * hreg[n + 1] + xv * sBC[w][buf][n + 1];
            y0 += hreg[n]     * sBC[w][buf][16 + n];
            y1 += hreg[n + 1] * sBC[w][buf][16 + n + 1];
        }
        g_yloc[(size_t)m * DINNER + d] = y0 + y1;
        if (p == 0) g_Dt[m * NHEADS + h] = runD;
        sBC[w][buf ^ 1][lane] = bc1;
        __syncwarp();
        buf ^= 1; xv = xv1; da = da1;
    }
    const int sb = ((b * NCHUNK + c) * NHEADS + h) * HEADDIM + p;
#pragma unroll
    for (int n = 0; n < DSTATE; n++) g_S[(size_t)sb * DSTATE + n] = hreg[n];
    if (p == 0) g_P[(b * NCHUNK + c) * NHEADS + h] = runD;
}

// ---------------- scan phase 2 (prefetched serial recurrence) ---------------
__global__ __launch_bounds__(1024) void scan_phase2()
{
    const int b = blockIdx.x >> 3, h = blockIdx.x & 7;
    const int tid = threadIdx.x;
    float val = 0.f;
    size_t base0 = (size_t)((b * NCHUNK + 0) * NHEADS + h) * (HEADDIM * DSTATE) + tid;
    const size_t stride = (size_t)NHEADS * HEADDIM * DSTATE;
    float s = g_S[base0];
    float pp = g_P[(b * NCHUNK + 0) * NHEADS + h];
    for (int c = 0; c < NCHUNK; c++) {
        float s1 = 0.f, p1 = 0.f;
        if (c + 1 < NCHUNK) {
            s1 = g_S[base0 + (c + 1) * stride];
            p1 = g_P[(b * NCHUNK + c + 1) * NHEADS + h];
        }
        g_hinit[base0 + c * stride] = val;
        val = pp * val + s;
        s = s1; pp = p1;
    }
}

// ---------------- phase 3 + skip + gate + RMSnorm (float4) ------------------
__global__ __launch_bounds__(128) void fuse_y_norm(
    const float* __restrict__ Dp, const float* __restrict__ nw)
{
    const int m = blockIdx.x, tid = threadIdx.x;
    const int b = m >> 13, l = m & (LL - 1), c = l >> 6;   // QCHUNK=64
    const int h = tid >> 4, d4 = tid * 4, p4 = d4 & 63;
    __shared__ float sC[DSTATE];
    __shared__ float sred[5];
    if (tid < DSTATE) sC[tid] = g_xBCs[(size_t)m * CONVDIM + DINNER + DSTATE + tid];
    __syncthreads();

    const float* hi = &g_hinit[((size_t)((b * NCHUNK + c) * NHEADS + h) * HEADDIM + p4) * DSTATE];
    float corr[4];
#pragma unroll
    for (int q = 0; q < 4; q++) {
        const float* hr = hi + q * DSTATE;
        float acc = 0.f;
#pragma unroll
        for (int n = 0; n < DSTATE; n += 4) {
            float4 hv = *(const float4*)&hr[n];
            acc += hv.x * sC[n] + hv.y * sC[n+1] + hv.z * sC[n+2] + hv.w * sC[n+3];
        }
        corr[q] = acc;
    }
    const float Dtv = g_Dt[m * NHEADS + h];
    const float Dpv = Dp[h];
    float4 xh = *(const float4*)&g_xBCs[(size_t)m * CONVDIM + d4];
    float4 yl = *(const float4*)&g_yloc[(size_t)m * DINNER + d4];
    float4 z  = *(const float4*)&g_zx[(size_t)m * DPROJ + d4];
    float yg[4];
    yg[0] = (yl.x + Dtv * corr[0] + Dpv * xh.x) * (z.x / (1.f + expf(-z.x)));
    yg[1] = (yl.y + Dtv * corr[1] + Dpv * xh.y) * (z.y / (1.f + expf(-z.y)));
    yg[2] = (yl.z + Dtv * corr[2] + Dpv * xh.z) * (z.z / (1.f + expf(-z.z)));
    yg[3] = (yl.w + Dtv * corr[3] + Dpv * xh.w) * (z.w / (1.f + expf(-z.w)));

    float v = yg[0]*yg[0] + yg[1]*yg[1] + yg[2]*yg[2] + yg[3]*yg[3];
#pragma unroll
    for (int o = 16; o; o >>= 1) v += __shfl_xor_sync(0xffffffffu, v, o);
    if ((tid & 31) == 0) sred[tid >> 5] = v;
    __syncthreads();
    const float tot = sred[0] + sred[1] + sred[2] + sred[3];
    const float rstd = rsqrtf(tot * (1.f / (float)DINNER) + 1e-5f);

    float4 nwv = *(const float4*)&nw[d4];
    float4 o;
    o.x = f2tf_f(yg[0] * rstd * nwv.x);
    o.y = f2tf_f(yg[1] * rstd * nwv.y);
    o.z = f2tf_f(yg[2] * rstd * nwv.z);
    o.w = f2tf_f(yg[3] * rstd * nwv.w);
    *(float4*)&g_ynorm[(size_t)m * DINNER + d4] = o;
}

// ---------------- driver ---------------------------------------------------
extern "C" void kernel_launch(void* const* d_in, const int* in_sizes, int n_in,
                              void* d_out, int out_size)
{
    const float* x       = (const float*)d_in[0];
    const float* patch_w = (const float*)d_in[1];
    const float* patch_b = (const float*)d_in[2];
    const float* W_in    = (const float*)d_in[3];
    const float* conv_w  = (const float*)d_in[4];
    const float* conv_b  = (const float*)d_in[5];
    const float* dt_bias = (const float*)d_in[6];
    const float* A_log   = (const float*)d_in[7];
    const float* D_param = (const float*)d_in[8];
    const float* norm_w  = (const float*)d_in[9];
    const float* W_out   = (const float*)d_in[10];
    const float* unemb_w = (const float*)d_in[11];
    const float* unemb_b = (const float*)d_in[12];
    float* out = (float*)d_out;

    float *pWT, *pxs, *pzx, *pyn, *pos, *pWin, *pWout, *pWun;
    cudaGetSymbolAddress((void**)&pWT,   g_patchWT);
    cudaGetSymbolAddress((void**)&pxs,   g_xs);
    cudaGetSymbolAddress((void**)&pzx,   g_zx);
    cudaGetSymbolAddress((void**)&pyn,   g_ynorm);
    cudaGetSymbolAddress((void**)&pos,   g_outseq);
    cudaGetSymbolAddress((void**)&pWin,  g_Win_r);
    cudaGetSymbolAddress((void**)&pWout, g_Wout_r);
    cudaGetSymbolAddress((void**)&pWun,  g_Wun_r);

    cudaFuncSetAttribute(gemm_cp, cudaFuncAttributeMaxDynamicSharedMemorySize, GEMM_SMEM);
    cudaFuncSetAttribute(gemm_unembed, cudaFuncAttributeMaxDynamicSharedMemorySize, GEMM_SMEM);

    // weight prep (tf32 pre-rounding)
    transpose_pw<<<(KPATCH * DM + 255) / 256, 256>>>(patch_w);
    round_copy<<<(DM * DPROJ + 255) / 256, 256>>>(W_in, pWin, DM * DPROJ);
    round_copy<<<(DINNER * DM + 255) / 256, 256>>>(W_out, pWout, DINNER * DM);
    round_copy<<<(DM * KPATCH + 255) / 256, 256>>>(unemb_w, pWun, DM * KPATCH);

    // patch embed (fused im2col)
    patch_gemm<<<dim3(2, MTOK / 128), 256>>>(x, pWT, pxs, patch_b);

    // in_proj
    gemm_cp<<<dim3((DPROJ + 127) / 128, MTOK / 128), 256, GEMM_SMEM>>>(
        pxs, pWin, pzx, MTOK, DPROJ, DM, 0);

    // dt/dA + conv+silu+xdt
    dt_prep<<<(MTOK * NHEADS + 255) / 256, 256>>>(dt_bias, A_log);
    conv_v4<<<(MTOK * 136 + 255) / 256, 256>>>(conv_w, conv_b);

    // chunked SSM scan
    scan_phase1<<<dim3(NCHUNK, BB), 512>>>();
    scan_phase2<<<BB * NHEADS, 1024>>>();
    fuse_y_norm<<<MTOK, 128>>>(D_param, norm_w);

    // out_proj (output tf32-rounded for unembed)
    gemm_cp<<<dim3(2, MTOK / 128), 256, GEMM_SMEM>>>(
        pyn, pWout, pos, MTOK, DM, DINNER, 1);

    // unembed + scatter + bias + residual
    gemm_unembed<<<dim3(3, MTOK / 128), 256, GEMM_SMEM>>>(pos, pWun, x, unemb_b, out);
}

// round 7
// speedup vs baseline: 2.6553x; 1.0738x over previous
#include <cuda_runtime.h>
#include <math.h>
#include <stdint.h>

// ---------------- problem constants ----------------
#define BB      4
#define CIN     23
#define TT      8
#define HH      128
#define WW      128
#define DM      256
#define DSTATE  16
#define DCONV   4
#define DINNER  512
#define HEADDIM 64
#define NHEADS  8
#define CONVDIM 544
#define DPROJ   1064
#define HP      32
#define WP      32
#define LL      8192
#define MTOK    32768
#define KPATCH  368
#define QCHUNK  64
#define NCHUNK  128
#define NOUT    (BB*CIN*TT*HH*WW)

// ---------------- scratch ----------------
__device__ __align__(128) float g_patchWT[KPATCH * DM];
__device__ __align__(128) float g_Win_r [DM * DPROJ];
__device__ __align__(128) float g_Wout_r[DINNER * DM];
__device__ __align__(128) float g_Wun_r [DM * KPATCH];
__device__ __align__(128) float g_xs    [MTOK * DM];
__device__ __align__(128) float g_zx    [MTOK * DPROJ];
__device__ __align__(128) float g_xBCs  [MTOK * CONVDIM];
__device__ __align__(128) float g_dAdt  [MTOK * NHEADS * 2];   // (dA, dt) pairs
__device__ __align__(128) float g_Dt    [MTOK * NHEADS];
__device__ __align__(128) float g_yloc  [MTOK * DINNER];
__device__ __align__(128) float g_S     [BB*NCHUNK*NHEADS*HEADDIM*DSTATE];
__device__ __align__(128) float g_P     [BB*NCHUNK*NHEADS];
__device__ __align__(128) float g_hinit [BB*NCHUNK*NHEADS*HEADDIM*DSTATE];
__device__ __align__(128) float g_ynorm [MTOK * DINNER];
__device__ __align__(128) float g_outseq[MTOK * DM];

// ---------------- helpers ---------------------------------------------------
__device__ __forceinline__ uint32_t f2tf(float f) {
    uint32_t u;
    asm("cvt.rna.tf32.f32 %0, %1;" : "=r"(u) : "f"(f));
    return u;
}
__device__ __forceinline__ float f2tf_f(float f) { return __uint_as_float(f2tf(f)); }

__device__ __forceinline__ void mma8(float* c, const uint32_t* a, const uint32_t* b) {
    asm volatile(
        "mma.sync.aligned.m16n8k8.row.col.f32.tf32.tf32.f32 "
        "{%0,%1,%2,%3},{%4,%5,%6,%7},{%8,%9},{%0,%1,%2,%3};"
        : "+f"(c[0]), "+f"(c[1]), "+f"(c[2]), "+f"(c[3])
        : "r"(a[0]), "r"(a[1]), "r"(a[2]), "r"(a[3]), "r"(b[0]), "r"(b[1]));
}
__device__ __forceinline__ void ldsm4(uint32_t* r, uint32_t addr) {
    asm volatile("ldmatrix.sync.aligned.m8n8.x4.shared.b16 {%0,%1,%2,%3},[%4];"
                 : "=r"(r[0]), "=r"(r[1]), "=r"(r[2]), "=r"(r[3]) : "r"(addr));
}
__device__ __forceinline__ void cpasync16(uint32_t saddr, const void* gaddr) {
    asm volatile("cp.async.cg.shared.global [%0], [%1], 16;\n" :: "r"(saddr), "l"(gaddr));
}
__device__ __forceinline__ void cpasync16z(uint32_t saddr, const void* gaddr, int sz) {
    asm volatile("cp.async.cg.shared.global [%0], [%1], 16, %2;\n"
                 :: "r"(saddr), "l"(gaddr), "r"(sz));
}
#define CP_COMMIT() asm volatile("cp.async.commit_group;\n" ::: "memory")
#define CP_WAIT2()  asm volatile("cp.async.wait_group 2;\n" ::: "memory")

#define ASTG 2560   // 128*20
#define BSTG 2176   // 16*136
#define GEMM_SMEM ((4*ASTG + 4*BSTG) * 4)

// ---------------- generic cp.async TF32 GEMM (inputs pre-rounded) ----------
__global__ __launch_bounds__(256, 2) void gemm_cp(
    const float* __restrict__ A, const float* __restrict__ B,
    float* __restrict__ C, int M, int N, int K, int roundOut)
{
    extern __shared__ uint32_t sm[];
    const uint32_t smb = (uint32_t)__cvta_generic_to_shared(sm);
    const int tid = threadIdx.x, warp = tid >> 5, lane = tid & 31;
    const int warpM = warp >> 2, warpN = warp & 3;
    const int g = lane >> 2, t4 = lane & 3;
    const int bm = blockIdx.y * 128, bn = blockIdx.x * 128;
    const int aRow = tid >> 2, aK = (tid & 3) * 4;
    const int bK = tid >> 5, bCol = (tid & 31) * 4;
    const int bsz = (bn + bCol) < N ? 16 : 0;
    const int T = K >> 4;

    float acc[4][4][4];
#pragma unroll
    for (int i = 0; i < 4; i++)
#pragma unroll
        for (int j = 0; j < 4; j++)
#pragma unroll
            for (int q = 0; q < 4; q++) acc[i][j][q] = 0.f;

#define ISSUE(t) { \
    int s_ = (t) & 3; int k0_ = (t) << 4; \
    uint32_t sa_ = smb + s_ * (ASTG * 4); \
    uint32_t sb_ = smb + (4 * ASTG * 4) + s_ * (BSTG * 4); \
    cpasync16(sa_ + (aRow * 20 + aK) * 4, &A[(size_t)(bm + aRow) * K + k0_ + aK]); \
    cpasync16(sa_ + ((aRow + 64) * 20 + aK) * 4, &A[(size_t)(bm + aRow + 64) * K + k0_ + aK]); \
    cpasync16z(sb_ + (bK * 136 + bCol) * 4, &B[(size_t)(k0_ + bK) * N + bn + bCol], bsz); \
    cpasync16z(sb_ + ((bK + 8) * 136 + bCol) * 4, &B[(size_t)(k0_ + bK + 8) * N + bn + bCol], bsz); }

    ISSUE(0); CP_COMMIT();
    ISSUE(1); CP_COMMIT();
    ISSUE(2); CP_COMMIT();
    CP_WAIT2();
    __syncthreads();

    for (int t = 0; t < T; t++) {
        const int s = t & 3;
        const uint32_t sa = smb + s * (ASTG * 4);
        const uint32_t* Bs = sm + 4 * ASTG + s * BSTG;
#pragma unroll
        for (int kk = 0; kk < 16; kk += 8) {
            uint32_t af[4][4], bf[4][2];
#pragma unroll
            for (int i = 0; i < 4; i++) {
                const int m0 = warpM * 64 + i * 16;
                ldsm4(af[i], sa + ((m0 + (lane & 15)) * 20 + kk + ((lane & 16) >> 2)) * 4);
            }
#pragma unroll
            for (int j = 0; j < 4; j++) {
                const int n0 = warpN * 32 + j * 8;
                bf[j][0] = Bs[(kk + t4) * 136 + n0 + g];
                bf[j][1] = Bs[(kk + t4 + 4) * 136 + n0 + g];
            }
#pragma unroll
            for (int i = 0; i < 4; i++)
#pragma unroll
                for (int j = 0; j < 4; j++)
                    mma8(acc[i][j], af[i], bf[j]);
        }
        if (t + 3 < T) ISSUE(t + 3);
        CP_COMMIT();
        CP_WAIT2();
        __syncthreads();
    }
#undef ISSUE

#pragma unroll
    for (int i = 0; i < 4; i++) {
        const int r0 = bm + warpM * 64 + i * 16 + g;
#pragma unroll
        for (int j = 0; j < 4; j++) {
            const int c0 = bn + warpN * 32 + j * 8 + t4 * 2;
            if (c0 + 1 < N) {
                float v0 = acc[i][j][0], v1 = acc[i][j][1];
                float v2 = acc[i][j][2], v3 = acc[i][j][3];
                if (roundOut) { v0 = f2tf_f(v0); v1 = f2tf_f(v1); v2 = f2tf_f(v2); v3 = f2tf_f(v3); }
                *(float2*)&C[(size_t)r0 * N + c0] = make_float2(v0, v1);
                *(float2*)&C[(size_t)(r0 + 8) * N + c0] = make_float2(v2, v3);
            } else if (c0 < N) {
                float v0 = acc[i][j][0], v2 = acc[i][j][2];
                if (roundOut) { v0 = f2tf_f(v0); v2 = f2tf_f(v2); }
                C[(size_t)r0 * N + c0] = v0;
                C[(size_t)(r0 + 8) * N + c0] = v2;
            }
        }
    }
}

// ---------------- unembed GEMM with fused scatter + residual epilogue ------
__global__ __launch_bounds__(256, 2) void gemm_unembed(
    const float* __restrict__ A, const float* __restrict__ B,
    const float* __restrict__ x, const float* __restrict__ ub,
    float* __restrict__ out)
{
    const int N = KPATCH, K = DM;
    extern __shared__ uint32_t sm[];
    const uint32_t smb = (uint32_t)__cvta_generic_to_shared(sm);
    const int tid = threadIdx.x, warp = tid >> 5, lane = tid & 31;
    const int warpM = warp >> 2, warpN = warp & 3;
    const int g = lane >> 2, t4 = lane & 3;
    const int bm = blockIdx.y * 128, bn = blockIdx.x * 128;
    const int aRow = tid >> 2, aK = (tid & 3) * 4;
    const int bK = tid >> 5, bCol = (tid & 31) * 4;
    const int bsz = (bn + bCol) < N ? 16 : 0;
    const int T = K >> 4;

    float acc[4][4][4];
#pragma unroll
    for (int i = 0; i < 4; i++)
#pragma unroll
        for (int j = 0; j < 4; j++)
#pragma unroll
            for (int q = 0; q < 4; q++) acc[i][j][q] = 0.f;

#define ISSUE(t) { \
    int s_ = (t) & 3; int k0_ = (t) << 4; \
    uint32_t sa_ = smb + s_ * (ASTG * 4); \
    uint32_t sb_ = smb + (4 * ASTG * 4) + s_ * (BSTG * 4); \
    cpasync16(sa_ + (aRow * 20 + aK) * 4, &A[(size_t)(bm + aRow) * K + k0_ + aK]); \
    cpasync16(sa_ + ((aRow + 64) * 20 + aK) * 4, &A[(size_t)(bm + aRow + 64) * K + k0_ + aK]); \
    cpasync16z(sb_ + (bK * 136 + bCol) * 4, &B[(size_t)(k0_ + bK) * N + bn + bCol], bsz); \
    cpasync16z(sb_ + ((bK + 8) * 136 + bCol) * 4, &B[(size_t)(k0_ + bK + 8) * N + bn + bCol], bsz); }

    ISSUE(0); CP_COMMIT();
    ISSUE(1); CP_COMMIT();
    ISSUE(2); CP_COMMIT();
    CP_WAIT2();
    __syncthreads();

    for (int t = 0; t < T; t++) {
        const int s = t & 3;
        const uint32_t sa = smb + s * (ASTG * 4);
        const uint32_t* Bs = sm + 4 * ASTG + s * BSTG;
#pragma unroll
        for (int kk = 0; kk < 16; kk += 8) {
            uint32_t af[4][4], bf[4][2];
#pragma unroll
            for (int i = 0; i < 4; i++) {
                const int m0 = warpM * 64 + i * 16;
                ldsm4(af[i], sa + ((m0 + (lane & 15)) * 20 + kk + ((lane & 16) >> 2)) * 4);
            }
#pragma unroll
            for (int j = 0; j < 4; j++) {
                const int n0 = warpN * 32 + j * 8;
                bf[j][0] = Bs[(kk + t4) * 136 + n0 + g];
                bf[j][1] = Bs[(kk + t4 + 4) * 136 + n0 + g];
            }
#pragma unroll
            for (int i = 0; i < 4; i++)
#pragma unroll
                for (int j = 0; j < 4; j++)
                    mma8(acc[i][j], af[i], bf[j]);
        }
        if (t + 3 < T) ISSUE(t + 3);
        CP_COMMIT();
        CP_WAIT2();
        __syncthreads();
    }
#undef ISSUE

#pragma unroll
    for (int i = 0; i < 4; i++) {
        const int r0 = bm + warpM * 64 + i * 16 + g;
        const int wp = r0 & 31, hp = (r0 >> 5) & 31, tt = (r0 >> 10) & 7, b = r0 >> 13;
#pragma unroll
        for (int j = 0; j < 4; j++) {
            const int c0 = bn + warpN * 32 + j * 8 + t4 * 2;
            if (c0 < N) {
                const int c = c0 >> 4, i4 = (c0 >> 2) & 3, j0 = c0 & 3;
                const size_t o = ((((size_t)(b * CIN + c) * TT + tt) * HH) + hp * 4 + i4) * WW
                               + (size_t)wp * 4 + j0;
                const float ubv = ub[c];
                float2 xv0 = *(const float2*)&x[o];
                float2 xv1 = *(const float2*)&x[o + 32];
                *(float2*)&out[o]      = make_float2(acc[i][j][0] + ubv + xv0.x,
                                                     acc[i][j][1] + ubv + xv0.y);
                *(float2*)&out[o + 32] = make_float2(acc[i][j][2] + ubv + xv1.x,
                                                     acc[i][j][3] + ubv + xv1.y);
            }
        }
    }
}

// ---------------- patch-embed GEMM with fused im2col A-gather --------------
__global__ __launch_bounds__(256, 2) void patch_gemm(
    const float* __restrict__ x, const float* __restrict__ B,
    float* __restrict__ C, const float* __restrict__ bias)
{
    const int K = KPATCH, N = DM;
    __shared__ uint32_t As[2][128][20];
    __shared__ uint32_t Bs[2][16][136];
    const int tid = threadIdx.x, warp = tid >> 5, lane = tid & 31;
    const int warpM = warp >> 2, warpN = warp & 3;
    const int g = lane >> 2, t4 = lane & 3;
    const int bm = blockIdx.y * 128, bn = blockIdx.x * 128;
    const int aRow = tid >> 2, aK = (tid & 3) * 4;
    const int bK = tid >> 5, bCol = (tid & 31) * 4;

    const uint32_t asb = (uint32_t)__cvta_generic_to_shared(&As[0][0][0]);

    auto xoff = [&](int row, int k) -> size_t {
        const int c = k >> 4, i = (k >> 2) & 3;
        const int wp = row & 31, hp = (row >> 5) & 31, tt = (row >> 10) & 7, b = row >> 13;
        return ((((size_t)(b * CIN + c) * TT + tt) * HH) + hp * 4 + i) * WW + (size_t)wp * 4;
    };

    float acc[4][4][4];
#pragma unroll
    for (int i = 0; i < 4; i++)
#pragma unroll
        for (int j = 0; j < 4; j++)
#pragma unroll
            for (int q = 0; q < 4; q++) acc[i][j][q] = 0.f;

    {
        float4 av0 = *(const float4*)&x[xoff(bm + aRow, aK)];
        float4 av1 = *(const float4*)&x[xoff(bm + aRow + 64, aK)];
        float4 bv0 = *(const float4*)&B[(size_t)bK * N + bn + bCol];
        float4 bv1 = *(const float4*)&B[(size_t)(bK + 8) * N + bn + bCol];
        As[0][aRow][aK+0]=f2tf(av0.x); As[0][aRow][aK+1]=f2tf(av0.y);
        As[0][aRow][aK+2]=f2tf(av0.z); As[0][aRow][aK+3]=f2tf(av0.w);
        As[0][aRow+64][aK+0]=f2tf(av1.x); As[0][aRow+64][aK+1]=f2tf(av1.y);
        As[0][aRow+64][aK+2]=f2tf(av1.z); As[0][aRow+64][aK+3]=f2tf(av1.w);
        *(float4*)&Bs[0][bK][bCol]   = bv0;
        *(float4*)&Bs[0][bK+8][bCol] = bv1;
    }
    __syncthreads();

    int p = 0;
    for (int k0 = 0; k0 < K; k0 += 16) {
        const int kn = (k0 + 16 < K) ? (k0 + 16) : 0;
        float4 av0 = *(const float4*)&x[xoff(bm + aRow, kn + aK)];
        float4 av1 = *(const float4*)&x[xoff(bm + aRow + 64, kn + aK)];
        float4 bv0 = *(const float4*)&B[(size_t)(kn + bK) * N + bn + bCol];
        float4 bv1 = *(const float4*)&B[(size_t)(kn + bK + 8) * N + bn + bCol];

        const uint32_t sa = asb + (uint32_t)p * (128 * 20 * 4);
#pragma unroll
        for (int kk = 0; kk < 16; kk += 8) {
            uint32_t af[4][4], bf[4][2];
#pragma unroll
            for (int i = 0; i < 4; i++) {
                const int m0 = warpM * 64 + i * 16;
                ldsm4(af[i], sa + ((m0 + (lane & 15)) * 20 + kk + ((lane & 16) >> 2)) * 4);
            }
#pragma unroll
            for (int j = 0; j < 4; j++) {
                const int n0 = warpN * 32 + j * 8;
                bf[j][0] = Bs[p][kk + t4][n0 + g];
                bf[j][1] = Bs[p][kk + t4 + 4][n0 + g];
            }
#pragma unroll
            for (int i = 0; i < 4; i++)
#pragma unroll
                for (int j = 0; j < 4; j++)
                    mma8(acc[i][j], af[i], bf[j]);
        }

        const int q = p ^ 1;
        As[q][aRow][aK+0]=f2tf(av0.x); As[q][aRow][aK+1]=f2tf(av0.y);
        As[q][aRow][aK+2]=f2tf(av0.z); As[q][aRow][aK+3]=f2tf(av0.w);
        As[q][aRow+64][aK+0]=f2tf(av1.x); As[q][aRow+64][aK+1]=f2tf(av1.y);
        As[q][aRow+64][aK+2]=f2tf(av1.z); As[q][aRow+64][aK+3]=f2tf(av1.w);
        *(float4*)&Bs[q][bK][bCol]   = bv0;
        *(float4*)&Bs[q][bK+8][bCol] = bv1;
        __syncthreads();
        p = q;
    }

#pragma unroll
    for (int i = 0; i < 4; i++) {
        const int r0 = bm + warpM * 64 + i * 16 + g;
#pragma unroll
        for (int j = 0; j < 4; j++) {
            const int c0 = bn + warpN * 32 + j * 8 + t4 * 2;
            float2 bb = *(const float2*)&bias[c0];
            *(float2*)&C[(size_t)r0 * N + c0] =
                make_float2(f2tf_f(acc[i][j][0] + bb.x), f2tf_f(acc[i][j][1] + bb.y));
            *(float2*)&C[(size_t)(r0 + 8) * N + c0] =
                make_float2(f2tf_f(acc[i][j][2] + bb.x), f2tf_f(acc[i][j][3] + bb.y));
        }
    }
}

// ---------------- weight prep ----------------------------------------------
__global__ void transpose_pw(const float* __restrict__ pw)
{
    int idx = blockIdx.x * blockDim.x + threadIdx.x;
    if (idx >= KPATCH * DM) return;
    int k = idx / DM, n = idx % DM;
    g_patchWT[idx] = f2tf_f(pw[n * KPATCH + k]);
}
#define NW1 (DM * DPROJ)
#define NW2 (DINNER * DM)
#define NW3 (DM * KPATCH)
__global__ void round_all(const float* __restrict__ w1, const float* __restrict__ w2,
                          const float* __restrict__ w3)
{
    int i = blockIdx.x * blockDim.x + threadIdx.x;
    if (i < NW1) g_Win_r[i] = f2tf_f(w1[i]);
    else if (i < NW1 + NW2) g_Wout_r[i - NW1] = f2tf_f(w2[i - NW1]);
    else if (i < NW1 + NW2 + NW3) g_Wun_r[i - NW1 - NW2] = f2tf_f(w3[i - NW1 - NW2]);
}

// ---------------- tiled conv1d(w=4)+silu + fused dt/dA (dynamic smem) -------
#define CTOK 16
#define SXS  552   // halo row stride (floats)
#define CONV_SMEM (((CTOK + 3) * SXS + DCONV * CONVDIM + CONVDIM) * 4)  // 52832 B
__global__ __launch_bounds__(256) void conv_tiled(
    const float* __restrict__ cw, const float* __restrict__ cb,
    const float* __restrict__ dtb, const float* __restrict__ alog)
{
    extern __shared__ float csm[];
    float* sx  = csm;                          // [(CTOK+3)][SXS]
    float* swt = csm + (CTOK + 3) * SXS;       // [DCONV][CONVDIM]
    float* sb  = swt + DCONV * CONVDIM;        // [CONVDIM]
    const int m0 = blockIdx.x * CTOK;
    const int l0 = m0 & (LL - 1);
    const int tid = threadIdx.x;

    for (int i = tid; i < CONVDIM; i += 256) {
        float4 w = *(const float4*)&cw[i * 4];
        swt[0 * CONVDIM + i] = w.x; swt[1 * CONVDIM + i] = w.y;
        swt[2 * CONVDIM + i] = w.z; swt[3 * CONVDIM + i] = w.w;
        sb[i] = cb[i];
    }
    for (int t = tid; t < (CTOK + 3) * 136; t += 256) {
        int r = t / 136, c4 = (t % 136) * 4;
        int mm = m0 - 3 + r;
        float4 v = make_float4(0.f, 0.f, 0.f, 0.f);
        if (l0 > 0 || r >= 3)
            v = *(const float4*)&g_zx[(size_t)mm * DPROJ + DINNER + c4];
        *(float4*)&sx[r * SXS + c4] = v;
    }
    if (tid < CTOK * NHEADS) {
        int tok = tid >> 3, hh = tid & 7;
        int m = m0 + tok;
        float raw = g_zx[(size_t)m * DPROJ + DINNER + CONVDIM + hh] + dtb[hh];
        float dt = (raw > 20.f) ? raw : log1pf(expf(raw));
        float da = expf(-expf(alog[hh]) * dt);
        *(float2*)&g_dAdt[(size_t)(m * NHEADS + hh) * 2] = make_float2(da, dt);
    }
    __syncthreads();

    for (int t = tid; t < CTOK * 136; t += 256) {
        int tok = t / 136, c4 = (t % 136) * 4;
        float4 acc = *(const float4*)&sb[c4];
#pragma unroll
        for (int k = 0; k < DCONV; k++) {
            float4 v = *(const float4*)&sx[(tok + k) * SXS + c4];
            float4 w = *(const float4*)&swt[k * CONVDIM + c4];
            acc.x += v.x * w.x; acc.y += v.y * w.y;
            acc.z += v.z * w.z; acc.w += v.w * w.w;
        }
        float4 s;
        s.x = acc.x / (1.f + expf(-acc.x));
        s.y = acc.y / (1.f + expf(-acc.y));
        s.z = acc.z / (1.f + expf(-acc.z));
        s.w = acc.w / (1.f + expf(-acc.w));
        *(float4*)&g_xBCs[(size_t)(m0 + tok) * CONVDIM + c4] = s;
    }
}

// ---------------- scan phase 1 (warp-autonomous, prefetched) ----------------
__global__ __launch_bounds__(512) void scan_phase1()
{
    const int c = blockIdx.x, b = blockIdx.y;
    const int w = threadIdx.x >> 5, lane = threadIdx.x & 31;
    const int h = w >> 1;
    const int p = ((w & 1) << 5) + lane;
    const int d = h * HEADDIM + p;
    __shared__ float sBC[16][2][32];
    float hreg[DSTATE];
#pragma unroll
    for (int n = 0; n < DSTATE; n++) hreg[n] = 0.f;
    float runD = 1.f;
    const int m0 = b * LL + c * QCHUNK;

    float sv = g_xBCs[(size_t)m0 * CONVDIM + d];
    float bc = g_xBCs[(size_t)m0 * CONVDIM + DINNER + lane];
    float2 dd = *(const float2*)&g_dAdt[(size_t)(m0 * NHEADS + h) * 2];
    sBC[w][0][lane] = bc;
    __syncwarp();

    int buf = 0;
    for (int i = 0; i < QCHUNK; i++) {
        const int m = m0 + i;
        float sv1 = 0.f, bc1 = 0.f;
        float2 dd1 = make_float2(0.f, 0.f);
        if (i + 1 < QCHUNK) {
            sv1 = g_xBCs[(size_t)(m + 1) * CONVDIM + d];
            bc1 = g_xBCs[(size_t)(m + 1) * CONVDIM + DINNER + lane];
            dd1 = *(const float2*)&g_dAdt[(size_t)((m + 1) * NHEADS + h) * 2];
        }
        const float da = dd.x;
        const float xv = sv * dd.y;
        runD *= da;
        float y0 = 0.f, y1 = 0.f;
#pragma unroll
        for (int n = 0; n < DSTATE; n += 2) {
            hreg[n]     = da * hreg[n]     + xv * sBC[w][buf][n];
            hreg[n + 1] = da * hreg[n + 1] + xv * sBC[w][buf][n + 1];
            y0 += hreg[n]     * sBC[w][buf][16 + n];
            y1 += hreg[n + 1] * sBC[w][buf][16 + n + 1];
        }
        g_yloc[(size_t)m * DINNER + d] = y0 + y1;
        if (p == 0) g_Dt[m * NHEADS + h] = runD;
        sBC[w][buf ^ 1][lane] = bc1;
        __syncwarp();
        buf ^= 1; sv = sv1; dd = dd1;
    }
    const int sb = ((b * NCHUNK + c) * NHEADS + h) * HEADDIM + p;
#pragma unroll
    for (int n = 0; n < DSTATE; n++) g_S[(size_t)sb * DSTATE + n] = hreg[n];
    if (p == 0) g_P[(b * NCHUNK + c) * NHEADS + h] = runD;
}

// ---------------- scan phase 2 (prefetched serial recurrence) ---------------
__global__ __launch_bounds__(1024) void scan_phase2()
{
    const int b = blockIdx.x >> 3, h = blockIdx.x & 7;
    const int tid = threadIdx.x;
    float val = 0.f;
    size_t base0 = (size_t)((b * NCHUNK + 0) * NHEADS + h) * (HEADDIM * DSTATE) + tid;
    const size_t stride = (size_t)NHEADS * HEADDIM * DSTATE;
    float s = g_S[base0];
    float pp = g_P[(b * NCHUNK + 0) * NHEADS + h];
    for (int c = 0; c < NCHUNK; c++) {
        float s1 = 0.f, p1 = 0.f;
        if (c + 1 < NCHUNK) {
            s1 = g_S[base0 + (c + 1) * stride];
            p1 = g_P[(b * NCHUNK + c + 1) * NHEADS + h];
        }
        g_hinit[base0 + c * stride] = val;
        val = pp * val + s;
        s = s1; pp = p1;
    }
}

// ---------------- phase 3 + skip + gate + RMSnorm (float4) ------------------
__global__ __launch_bounds__(128) void fuse_y_norm(
    const float* __restrict__ Dp, const float* __restrict__ nw)
{
    const int m = blockIdx.x, tid = threadIdx.x;
    const int b = m >> 13, l = m & (LL - 1), c = l >> 6;
    const int h = tid >> 4, d4 = tid * 4, p4 = d4 & 63;
    __shared__ float sC[DSTATE];
    __shared__ float sred[5];
    if (tid < DSTATE) sC[tid] = g_xBCs[(size_t)m * CONVDIM + DINNER + DSTATE + tid];
    __syncthreads();

    const float* hi = &g_hinit[((size_t)((b * NCHUNK + c) * NHEADS + h) * HEADDIM + p4) * DSTATE];
    float corr[4];
#pragma unroll
    for (int q = 0; q < 4; q++) {
        const float* hr = hi + q * DSTATE;
        float acc = 0.f;
#pragma unroll
        for (int n = 0; n < DSTATE; n += 4) {
            float4 hv = *(const float4*)&hr[n];
            acc += hv.x * sC[n] + hv.y * sC[n+1] + hv.z * sC[n+2] + hv.w * sC[n+3];
        }
        corr[q] = acc;
    }
    const float Dtv = g_Dt[m * NHEADS + h];
    const float Dpv = Dp[h];
    float4 xh = *(const float4*)&g_xBCs[(size_t)m * CONVDIM + d4];
    float4 yl = *(const float4*)&g_yloc[(size_t)m * DINNER + d4];
    float4 z  = *(const float4*)&g_zx[(size_t)m * DPROJ + d4];
    float yg[4];
    yg[0] = (yl.x + Dtv * corr[0] + Dpv * xh.x) * (z.x / (1.f + expf(-z.x)));
    yg[1] = (yl.y + Dtv * corr[1] + Dpv * xh.y) * (z.y / (1.f + expf(-z.y)));
    yg[2] = (yl.z + Dtv * corr[2] + Dpv * xh.z) * (z.z / (1.f + expf(-z.z)));
    yg[3] = (yl.w + Dtv * corr[3] + Dpv * xh.w) * (z.w / (1.f + expf(-z.w)));

    float v = yg[0]*yg[0] + yg[1]*yg[1] + yg[2]*yg[2] + yg[3]*yg[3];
#pragma unroll
    for (int o = 16; o; o >>= 1) v += __shfl_xor_sync(0xffffffffu, v, o);
    if ((tid & 31) == 0) sred[tid >> 5] = v;
    __syncthreads();
    const float tot = sred[0] + sred[1] + sred[2] + sred[3];
    const float rstd = rsqrtf(tot * (1.f / (float)DINNER) + 1e-5f);

    float4 nwv = *(const float4*)&nw[d4];
    float4 o;
    o.x = f2tf_f(yg[0] * rstd * nwv.x);
    o.y = f2tf_f(yg[1] * rstd * nwv.y);
    o.z = f2tf_f(yg[2] * rstd * nwv.z);
    o.w = f2tf_f(yg[3] * rstd * nwv.w);
    *(float4*)&g_ynorm[(size_t)m * DINNER + d4] = o;
}

// ---------------- driver ---------------------------------------------------
extern "C" void kernel_launch(void* const* d_in, const int* in_sizes, int n_in,
                              void* d_out, int out_size)
{
    const float* x       = (const float*)d_in[0];
    const float* patch_w = (const float*)d_in[1];
    const float* patch_b = (const float*)d_in[2];
    const float* W_in    = (const float*)d_in[3];
    const float* conv_w  = (const float*)d_in[4];
    const float* conv_b  = (const float*)d_in[5];
    const float* dt_bias = (const float*)d_in[6];
    const float* A_log   = (const float*)d_in[7];
    const float* D_param = (const float*)d_in[8];
    const float* norm_w  = (const float*)d_in[9];
    const float* W_out   = (const float*)d_in[10];
    const float* unemb_w = (const float*)d_in[11];
    const float* unemb_b = (const float*)d_in[12];
    float* out = (float*)d_out;

    float *pWT, *pxs, *pzx, *pyn, *pos, *pWin, *pWout, *pWun;
    cudaGetSymbolAddress((void**)&pWT,   g_patchWT);
    cudaGetSymbolAddress((void**)&pxs,   g_xs);
    cudaGetSymbolAddress((void**)&pzx,   g_zx);
    cudaGetSymbolAddress((void**)&pyn,   g_ynorm);
    cudaGetSymbolAddress((void**)&pos,   g_outseq);
    cudaGetSymbolAddress((void**)&pWin,  g_Win_r);
    cudaGetSymbolAddress((void**)&pWout, g_Wout_r);
    cudaGetSymbolAddress((void**)&pWun,  g_Wun_r);

    cudaFuncSetAttribute(gemm_cp, cudaFuncAttributeMaxDynamicSharedMemorySize, GEMM_SMEM);
    cudaFuncSetAttribute(gemm_unembed, cudaFuncAttributeMaxDynamicSharedMemorySize, GEMM_SMEM);
    cudaFuncSetAttribute(conv_tiled, cudaFuncAttributeMaxDynamicSharedMemorySize, CONV_SMEM);

    // weight prep (tf32 pre-rounding)
    transpose_pw<<<(KPATCH * DM + 255) / 256, 256>>>(patch_w);
    round_all<<<(NW1 + NW2 + NW3 + 255) / 256, 256>>>(W_in, W_out, unemb_w);

    // patch embed (fused im2col)
    patch_gemm<<<dim3(2, MTOK / 128), 256>>>(x, pWT, pxs, patch_b);

    // in_proj
    gemm_cp<<<dim3((DPROJ + 127) / 128, MTOK / 128), 256, GEMM_SMEM>>>(
        pxs, pWin, pzx, MTOK, DPROJ, DM, 0);

    // conv + silu + dt/dA (tiled, fused)
    conv_tiled<<<MTOK / CTOK, 256, CONV_SMEM>>>(conv_w, conv_b, dt_bias, A_log);

    // chunked SSM scan
    scan_phase1<<<dim3(NCHUNK, BB), 512>>>();
    scan_phase2<<<BB * NHEADS, 1024>>>();
    fuse_y_norm<<<MTOK, 128>>>(D_param, norm_w);

    // out_proj (output tf32-rounded for unembed)
    gemm_cp<<<dim3(2, MTOK / 128), 256, GEMM_SMEM>>>(
        pyn, pWout, pos, MTOK, DM, DINNER, 1);

    // unembed + scatter + bias + residual
    gemm_unembed<<<dim3(3, MTOK / 128), 256, GEMM_SMEM>>>(pos, pWun, x, unemb_b, out);
}